// round 1
// baseline (speedup 1.0000x reference)
#include <cuda_runtime.h>
#include <math.h>

// ---------------- problem constants (static per reference) ----------------
#define BB    4
#define NTOT  16384      // x spatial positions (128*128)
#define CC    256
#define NHH   8
#define HDD   32
#define NKV   1024       // (128/4)^2
#define KCONV 4096       // 16 * 256
#define TQ    16384
#define SCALE 0.17677669529663689f   // 32^-0.5

// ---------------- scratch (device globals; no allocation) ----------------
__device__ float g_wsr[KCONV * CC];           // conv weight transposed [k=(kh*4+kw)*256+ci][co]
__device__ float g_xr [BB * NKV * CC];        // conv+bias then LN'd  [4096][256]
__device__ float g_k  [BB * NHH * NKV * HDD]; // [b][h][pos][d]
__device__ float g_v  [BB * NHH * NKV * HDD];
__device__ float g_qh [TQ * CC];              // q projected [TQ][256]
__device__ float g_o  [TQ * CC];              // attention out [TQ][256]

// ---------------- weight transpose for conv GEMM ----------------
__global__ void k_transpose_srw(const float* __restrict__ srw) {
    int idx = blockIdx.x * 256 + threadIdx.x;          // 1M elements
    if (idx >= KCONV * CC) return;
    int co = idx % CC;
    int k  = idx / CC;
    int ci = k % CC;
    int p  = k / CC;                                   // kh*4+kw
    g_wsr[k * CC + co] = srw[(size_t)co * KCONV + ci * 16 + p];
}

// ---------------- generic 64x64x(K) fp32 GEMM core ----------------
// A row-major [M,K] (lda=K), B row-major [K,N] (ldb=N). 256 threads.
// acc[4][4] per thread; tx = tid%16 (4-col group), ty = tid/16 (4-row group).
__device__ __forceinline__ void gemm64x64(const float* __restrict__ A,
                                          const float* __restrict__ Bm,
                                          int K, int ldb,
                                          int m0, int n0,
                                          float acc[4][4]) {
    __shared__ float As[32][65];
    __shared__ float Bs[32][64];
    int tid = threadIdx.x;
    int tx = tid & 15, ty = tid >> 4;
    #pragma unroll
    for (int i = 0; i < 4; i++)
        #pragma unroll
        for (int j = 0; j < 4; j++) acc[i][j] = 0.f;

    for (int k0 = 0; k0 < K; k0 += 32) {
        #pragma unroll
        for (int i = 0; i < 8; i++) {
            int l = tid + i * 256;
            int r = l >> 5, kk = l & 31;
            As[kk][r] = A[(size_t)(m0 + r) * K + k0 + kk];
        }
        #pragma unroll
        for (int i = 0; i < 8; i++) {
            int l = tid + i * 256;
            int kk = l >> 6, nn = l & 63;
            Bs[kk][nn] = Bm[(size_t)(k0 + kk) * ldb + n0 + nn];
        }
        __syncthreads();
        #pragma unroll
        for (int kk = 0; kk < 32; kk++) {
            float4 bv = *(const float4*)&Bs[kk][tx * 4];
            float a0 = As[kk][ty * 4 + 0];
            float a1 = As[kk][ty * 4 + 1];
            float a2 = As[kk][ty * 4 + 2];
            float a3 = As[kk][ty * 4 + 3];
            acc[0][0] += a0 * bv.x; acc[0][1] += a0 * bv.y; acc[0][2] += a0 * bv.z; acc[0][3] += a0 * bv.w;
            acc[1][0] += a1 * bv.x; acc[1][1] += a1 * bv.y; acc[1][2] += a1 * bv.z; acc[1][3] += a1 * bv.w;
            acc[2][0] += a2 * bv.x; acc[2][1] += a2 * bv.y; acc[2][2] += a2 * bv.z; acc[2][3] += a2 * bv.w;
            acc[3][0] += a3 * bv.x; acc[3][1] += a3 * bv.y; acc[3][2] += a3 * bv.z; acc[3][3] += a3 * bv.w;
        }
        __syncthreads();
    }
}

// ---------------- conv-as-GEMM: g_xr = gather(x) @ g_wsr + sr_b ----------------
// M=4096 (b,oh,ow), K=4096 (=(kh*4+kw)*256+ci), N=256.
__global__ void __launch_bounds__(256) k_conv_gemm(const float* __restrict__ x,
                                                   const float* __restrict__ srb) {
    __shared__ float As[32][65];
    __shared__ float Bs[32][64];
    int tid = threadIdx.x;
    int tx = tid & 15, ty = tid >> 4;
    int n0 = blockIdx.x * 64, m0 = blockIdx.y * 64;
    float acc[4][4];
    #pragma unroll
    for (int i = 0; i < 4; i++)
        #pragma unroll
        for (int j = 0; j < 4; j++) acc[i][j] = 0.f;

    for (int k0 = 0; k0 < KCONV; k0 += 32) {
        int p   = k0 >> 8;          // pixel within 4x4 patch (constant per 32-wide k tile)
        int cib = k0 & 255;
        int kh = p >> 2, kw = p & 3;
        #pragma unroll
        for (int i = 0; i < 8; i++) {
            int l = tid + i * 256;
            int r = l >> 5, kk = l & 31;
            int m = m0 + r;
            int b = m >> 10, rem = m & 1023;
            int oh = rem >> 5, ow = rem & 31;
            size_t xi = ((size_t)(b * NTOT + (oh * 4 + kh) * 128 + (ow * 4 + kw))) * CC + cib + kk;
            As[kk][r] = x[xi];
        }
        #pragma unroll
        for (int i = 0; i < 8; i++) {
            int l = tid + i * 256;
            int kk = l >> 6, nn = l & 63;
            Bs[kk][nn] = g_wsr[(size_t)(k0 + kk) * CC + n0 + nn];
        }
        __syncthreads();
        #pragma unroll
        for (int kk = 0; kk < 32; kk++) {
            float4 bv = *(const float4*)&Bs[kk][tx * 4];
            float a0 = As[kk][ty * 4 + 0];
            float a1 = As[kk][ty * 4 + 1];
            float a2 = As[kk][ty * 4 + 2];
            float a3 = As[kk][ty * 4 + 3];
            acc[0][0] += a0 * bv.x; acc[0][1] += a0 * bv.y; acc[0][2] += a0 * bv.z; acc[0][3] += a0 * bv.w;
            acc[1][0] += a1 * bv.x; acc[1][1] += a1 * bv.y; acc[1][2] += a1 * bv.z; acc[1][3] += a1 * bv.w;
            acc[2][0] += a2 * bv.x; acc[2][1] += a2 * bv.y; acc[2][2] += a2 * bv.z; acc[2][3] += a2 * bv.w;
            acc[3][0] += a3 * bv.x; acc[3][1] += a3 * bv.y; acc[3][2] += a3 * bv.z; acc[3][3] += a3 * bv.w;
        }
        __syncthreads();
    }
    #pragma unroll
    for (int i = 0; i < 4; i++) {
        int m = m0 + ty * 4 + i;
        #pragma unroll
        for (int j = 0; j < 4; j++) {
            int n = n0 + tx * 4 + j;
            g_xr[(size_t)m * CC + n] = acc[i][j] + srb[n];
        }
    }
}

// ---------------- LayerNorm over C=256, in place on g_xr ----------------
__global__ void __launch_bounds__(256) k_layernorm(const float* __restrict__ gamma,
                                                   const float* __restrict__ beta) {
    int row  = blockIdx.x * 8 + (threadIdx.x >> 5);
    int lane = threadIdx.x & 31;
    float* xr = g_xr + (size_t)row * CC;
    float v[8];
    float s = 0.f;
    #pragma unroll
    for (int i = 0; i < 8; i++) { v[i] = xr[lane + i * 32]; s += v[i]; }
    #pragma unroll
    for (int o = 16; o; o >>= 1) s += __shfl_xor_sync(0xffffffffu, s, o);
    float mu = s * (1.f / 256.f);
    float s2 = 0.f;
    #pragma unroll
    for (int i = 0; i < 8; i++) { float d = v[i] - mu; s2 += d * d; }
    #pragma unroll
    for (int o = 16; o; o >>= 1) s2 += __shfl_xor_sync(0xffffffffu, s2, o);
    float rstd = rsqrtf(s2 * (1.f / 256.f) + 1e-5f);
    #pragma unroll
    for (int i = 0; i < 8; i++) {
        int c = lane + i * 32;
        xr[c] = (v[i] - mu) * rstd * gamma[c] + beta[c];
    }
}

// ---------------- KV projection with scatter to [b][h][pos][d] ----------------
__global__ void __launch_bounds__(256) k_kv_gemm(const float* __restrict__ wkv) {
    int n0 = blockIdx.x * 64, m0 = blockIdx.y * 64;
    float acc[4][4];
    gemm64x64(g_xr, wkv, CC, 2 * CC, m0, n0, acc);
    int tx = threadIdx.x & 15, ty = threadIdx.x >> 4;
    #pragma unroll
    for (int i = 0; i < 4; i++) {
        int m = m0 + ty * 4 + i;
        int b = m >> 10, pos = m & 1023;
        #pragma unroll
        for (int j = 0; j < 4; j++) {
            int n = n0 + tx * 4 + j;
            int half = n >> 8;
            int h = (n >> 5) & 7;
            int d = n & 31;
            size_t dst = ((size_t)((b * NHH + h) * NKV + pos)) * HDD + d;
            if (half == 0) g_k[dst] = acc[i][j];
            else           g_v[dst] = acc[i][j];
        }
    }
}

// ---------------- Q projection ----------------
__global__ void __launch_bounds__(256) k_qproj(const float* __restrict__ q,
                                               const float* __restrict__ wq) {
    int n0 = blockIdx.x * 64, m0 = blockIdx.y * 64;
    float acc[4][4];
    gemm64x64(q, wq, CC, CC, m0, n0, acc);
    int tx = threadIdx.x & 15, ty = threadIdx.x >> 4;
    #pragma unroll
    for (int i = 0; i < 4; i++)
        #pragma unroll
        for (int j = 0; j < 4; j++)
            g_qh[(size_t)(m0 + ty * 4 + i) * CC + n0 + tx * 4 + j] = acc[i][j];
}

// ---------------- Output projection + bias -> d_out ----------------
__global__ void __launch_bounds__(256) k_proj(const float* __restrict__ wp,
                                              const float* __restrict__ bp,
                                              float* __restrict__ out) {
    int n0 = blockIdx.x * 64, m0 = blockIdx.y * 64;
    float acc[4][4];
    gemm64x64(g_o, wp, CC, CC, m0, n0, acc);
    int tx = threadIdx.x & 15, ty = threadIdx.x >> 4;
    #pragma unroll
    for (int i = 0; i < 4; i++)
        #pragma unroll
        for (int j = 0; j < 4; j++) {
            int n = n0 + tx * 4 + j;
            out[(size_t)(m0 + ty * 4 + i) * CC + n] = acc[i][j] + bp[n];
        }
}

// ---------------- Attention: 32 queries x 1024 keys per block ----------------
// dyn smem: Ss[32][1024] + Qt[32(d)][36] + KVs(max(Kt[32][132],Vs[128][36])) + linv[32]
#define ATT_SS_F   (32 * 1024)
#define ATT_QT_F   (32 * 36)
#define ATT_KV_F   (128 * 36)
#define ATT_SMEM_BYTES ((ATT_SS_F + ATT_QT_F + ATT_KV_F + 32) * 4)

__global__ void __launch_bounds__(256) k_attn(const int* __restrict__ qlen) {
    extern __shared__ float sm[];
    float* Ss   = sm;                         // [32][1024]
    float* Qt   = Ss + ATT_SS_F;              // [d][row], stride 36
    float* KVs  = Qt + ATT_QT_F;              // Kt [d][key] stride 132 / Vs [key][d] stride 36
    float* linv = KVs + ATT_KV_F;             // [32]

    int tid = threadIdx.x;
    int h   = blockIdx.y;
    int q0  = blockIdx.x * 32;

    // ragged batch lookup (lengths are multiples of 32; a tile never spans batches)
    int l0 = qlen[0], l1 = qlen[1], l2 = qlen[2];
    int off = 0, b = 0;
    if (q0 >= l0)           { off = l0;           b = 1; }
    if (q0 >= l0 + l1)      { off = l0 + l1;      b = 2; }
    if (q0 >= l0 + l1 + l2) { off = l0 + l1 + l2; b = 3; }
    (void)off;

    const float* Kb = g_k + ((size_t)(b * NHH + h) * NKV) * HDD;
    const float* Vb = g_v + ((size_t)(b * NHH + h) * NKV) * HDD;

    // stage Q tile transposed: Qt[d][r]
    #pragma unroll
    for (int i = 0; i < 4; i++) {
        int e = tid + i * 256;
        int r = e >> 5, d = e & 31;
        Qt[d * 36 + r] = g_qh[(size_t)(q0 + r) * CC + h * HDD + d];
    }

    int tx = tid & 31;   // 32 col-groups of 4 (128 keys/tile)
    int ty = tid >> 5;   // 8 row-groups of 4 (32 queries)

    // ---- S = Q @ K^T over 8 key tiles of 128 ----
    for (int kt = 0; kt < 8; kt++) {
        int j0 = kt * 128;
        __syncthreads();
        #pragma unroll
        for (int i = 0; i < 16; i++) {
            int e = tid + i * 256;
            int key = e >> 5, d = e & 31;
            KVs[d * 132 + key] = Kb[(size_t)(j0 + key) * HDD + d];   // transposed
        }
        __syncthreads();
        float acc[4][4];
        #pragma unroll
        for (int i = 0; i < 4; i++)
            #pragma unroll
            for (int j = 0; j < 4; j++) acc[i][j] = 0.f;
        #pragma unroll
        for (int kk = 0; kk < 32; kk++) {
            float4 av = *(const float4*)&Qt [kk * 36  + ty * 4];
            float4 bv = *(const float4*)&KVs[kk * 132 + tx * 4];
            acc[0][0] += av.x * bv.x; acc[0][1] += av.x * bv.y; acc[0][2] += av.x * bv.z; acc[0][3] += av.x * bv.w;
            acc[1][0] += av.y * bv.x; acc[1][1] += av.y * bv.y; acc[1][2] += av.y * bv.z; acc[1][3] += av.y * bv.w;
            acc[2][0] += av.z * bv.x; acc[2][1] += av.z * bv.y; acc[2][2] += av.z * bv.z; acc[2][3] += av.z * bv.w;
            acc[3][0] += av.w * bv.x; acc[3][1] += av.w * bv.y; acc[3][2] += av.w * bv.z; acc[3][3] += av.w * bv.w;
        }
        #pragma unroll
        for (int i = 0; i < 4; i++)
            #pragma unroll
            for (int j = 0; j < 4; j++)
                Ss[(ty * 4 + i) * 1024 + j0 + tx * 4 + j] = acc[i][j];
    }
    __syncthreads();

    // ---- softmax (unnormalized exp stored; 1/l folded into epilogue) ----
    int warp = tid >> 5, lane = tid & 31;
    for (int rr = 0; rr < 4; rr++) {
        int r = warp * 4 + rr;
        float* row = Ss + r * 1024;
        float m = -1e30f;
        for (int j = lane; j < 1024; j += 32) m = fmaxf(m, row[j]);
        #pragma unroll
        for (int o = 16; o; o >>= 1) m = fmaxf(m, __shfl_xor_sync(0xffffffffu, m, o));
        float s = 0.f;
        for (int j = lane; j < 1024; j += 32) {
            float p = __expf((row[j] - m) * SCALE);
            row[j] = p;
            s += p;
        }
        #pragma unroll
        for (int o = 16; o; o >>= 1) s += __shfl_xor_sync(0xffffffffu, s, o);
        if (lane == 0) linv[r] = 1.f / s;
    }
    __syncthreads();

    // ---- O = P @ V over 8 value tiles of 128 ----
    int r  = tid >> 3;            // 32 rows
    int g4 = (tid & 7) * 4;       // 8 col-groups of 4 (32 dims)
    float acc[4] = {0.f, 0.f, 0.f, 0.f};
    for (int kt = 0; kt < 8; kt++) {
        int j0 = kt * 128;
        __syncthreads();
        #pragma unroll
        for (int i = 0; i < 16; i++) {
            int e = tid + i * 256;
            int key = e >> 5, d = e & 31;
            KVs[key * 36 + d] = Vb[(size_t)(j0 + key) * HDD + d];
        }
        __syncthreads();
        const float* prow = Ss + r * 1024 + j0;
        #pragma unroll 4
        for (int j = 0; j < 128; j += 4) {
            float4 p4 = *(const float4*)&prow[j];
            float pu[4] = {p4.x, p4.y, p4.z, p4.w};
            #pragma unroll
            for (int u = 0; u < 4; u++) {
                float4 vv = *(const float4*)&KVs[(j + u) * 36 + g4];
                acc[0] += pu[u] * vv.x;
                acc[1] += pu[u] * vv.y;
                acc[2] += pu[u] * vv.z;
                acc[3] += pu[u] * vv.w;
            }
        }
    }
    float li = linv[r];
    #pragma unroll
    for (int i = 0; i < 4; i++)
        g_o[(size_t)(q0 + r) * CC + h * HDD + g4 + i] = acc[i] * li;
}

// ---------------- launch ----------------
extern "C" void kernel_launch(void* const* d_in, const int* in_sizes, int n_in,
                              void* d_out, int out_size) {
    const float* x      = (const float*)d_in[0];
    const float* q      = (const float*)d_in[1];
    // d_in[2]=H, d_in[3]=W (128/128, unused)
    const int*   qlen   = (const int*)  d_in[4];
    const float* w_q    = (const float*)d_in[5];
    const float* w_kv   = (const float*)d_in[6];
    const float* sr_w   = (const float*)d_in[7];
    const float* sr_b   = (const float*)d_in[8];
    const float* ln_g   = (const float*)d_in[9];
    const float* ln_b   = (const float*)d_in[10];
    const float* proj_w = (const float*)d_in[11];
    const float* proj_b = (const float*)d_in[12];
    float* out = (float*)d_out;

    cudaFuncSetAttribute(k_attn, cudaFuncAttributeMaxDynamicSharedMemorySize, ATT_SMEM_BYTES);

    k_transpose_srw<<<(KCONV * CC + 255) / 256, 256>>>(sr_w);
    k_conv_gemm<<<dim3(CC / 64, (BB * NKV) / 64), 256>>>(x, sr_b);
    k_layernorm<<<(BB * NKV) / 8, 256>>>(ln_g, ln_b);
    k_kv_gemm<<<dim3((2 * CC) / 64, (BB * NKV) / 64), 256>>>(w_kv);
    k_qproj<<<dim3(CC / 64, TQ / 64), 256>>>(q, w_q);
    k_attn<<<dim3(TQ / 32, NHH), 256, ATT_SMEM_BYTES>>>(qlen);
    k_proj<<<dim3(CC / 64, TQ / 64), 256>>>(proj_w, proj_b, out);
}

// round 4
// speedup vs baseline: 1.9794x; 1.9794x over previous
#include <cuda_runtime.h>
#include <cuda_fp16.h>
#include <math.h>
#include <stdint.h>

#define BB    4
#define NTOT  16384
#define CC    256
#define NHH   8
#define HDD   32
#define NKV   1024
#define KCONV 4096
#define TQ    16384
#define SCALE 0.17677669529663689f

// ---------------- scratch (device globals) ----------------
__device__ __half g_xh [BB*NTOT*CC], g_xl [BB*NTOT*CC];  // x split (FULL batch!)
__device__ __half g_qih[TQ*CC],   g_qil[TQ*CC];
__device__ __half g_wqh[CC*CC],   g_wql[CC*CC];
__device__ __half g_wkvh[CC*2*CC],g_wkvl[CC*2*CC];
__device__ __half g_pwh[CC*CC],   g_pwl[CC*CC];
__device__ __half g_wsrh[KCONV*CC], g_wsrl[KCONV*CC];
__device__ float  g_xr [BB*NKV*CC];
__device__ __half g_xrh[BB*NKV*CC], g_xrl[BB*NKV*CC];
__device__ __half g_kh [BB*NHH*NKV*HDD], g_vh[BB*NHH*NKV*HDD]; // [b][h][pos][d]
__device__ __half g_qhh[TQ*CC];
__device__ __half g_oh [TQ*CC], g_ol[TQ*CC];

// ---------------- helpers ----------------
__device__ __forceinline__ void fsplit(float x, __half& h, __half& l) {
    h = __float2half_rn(x);
    l = __float2half_rn(x - __half2float(h));
}

__device__ __forceinline__ void mma16816(float* c,
    uint32_t a0, uint32_t a1, uint32_t a2, uint32_t a3, uint32_t b0, uint32_t b1) {
    asm volatile("mma.sync.aligned.m16n8k16.row.col.f32.f16.f16.f32 "
        "{%0,%1,%2,%3}, {%4,%5,%6,%7}, {%8,%9}, {%0,%1,%2,%3};\n"
        : "+f"(c[0]), "+f"(c[1]), "+f"(c[2]), "+f"(c[3])
        : "r"(a0), "r"(a1), "r"(a2), "r"(a3), "r"(b0), "r"(b1));
}

__device__ __forceinline__ uint32_t pack2(__half lo, __half hi) {
    __half2 t = __halves2half2(lo, hi);
    return *(uint32_t*)&t;
}

// ---------------- convert kernels ----------------
__global__ void k_split(const float* __restrict__ src, __half* __restrict__ dh,
                        __half* __restrict__ dl, int n) {
    int i = blockIdx.x * 256 + threadIdx.x;
    if (i < n) { __half h, l; fsplit(src[i], h, l); dh[i] = h; dl[i] = l; }
}

__global__ void k_split_srw(const float* __restrict__ srw) {
    int idx = blockIdx.x * 256 + threadIdx.x;
    if (idx >= KCONV * CC) return;
    int co = idx & 255;
    int k  = idx >> 8;
    int ci = k & 255;
    int p  = k >> 8;
    float v = srw[(size_t)co * KCONV + ci * 16 + p];
    __half h, l; fsplit(v, h, l);
    g_wsrh[idx] = h; g_wsrl[idx] = l;
}

// ---------------- smem tile loaders (BM=128, BN=64, BK=32; stride 40 halves) ----------------
__device__ __forceinline__ void load_A(const __half* __restrict__ Ah, const __half* __restrict__ Al,
                                       int K, int m0, int k0, __half* Ash, __half* Asl) {
    int tid = threadIdx.x;
    #pragma unroll
    for (int i = 0; i < 8; i++) {
        int l = tid + i * 256;
        int m = l >> 4, kp = l & 15;
        size_t g = (size_t)(m0 + m) * K + k0 + kp * 2;
        ((uint32_t*)Ash)[m * 20 + kp] = *(const uint32_t*)(Ah + g);
        ((uint32_t*)Asl)[m * 20 + kp] = *(const uint32_t*)(Al + g);
    }
}

__device__ __forceinline__ void load_B(const __half* __restrict__ Bh, const __half* __restrict__ Bl,
                                       int N, int k0, int n0, __half* Bsh, __half* Bsl) {
    int tid = threadIdx.x;
    #pragma unroll
    for (int i = 0; i < 8; i++) {
        int l = tid + i * 256;
        int kk = l >> 6, n = l & 63;
        size_t g = (size_t)(k0 + kk) * N + n0 + n;
        Bsh[n * 40 + kk] = Bh[g];
        Bsl[n * 40 + kk] = Bl[g];
    }
}

// 3-mma split compute for one BK=32 step. warp tile 32x32 (2 m16 x 4 n8).
__device__ __forceinline__ void mma_step32(const __half* Ash, const __half* Asl,
                                           const __half* Bsh, const __half* Bsl,
                                           float acc[2][4][4], int wm, int wn,
                                           int gid, int tig) {
    #pragma unroll
    for (int ks = 0; ks < 32; ks += 16) {
        int c = ks + tig * 2;
        uint32_t ah[2][4], al[2][4], bh[4][2], bl[4][2];
        #pragma unroll
        for (int mt = 0; mt < 2; mt++) {
            int r0 = wm * 32 + mt * 16 + gid;
            ah[mt][0] = *(const uint32_t*)(Ash + r0 * 40 + c);
            ah[mt][1] = *(const uint32_t*)(Ash + (r0 + 8) * 40 + c);
            ah[mt][2] = *(const uint32_t*)(Ash + r0 * 40 + c + 8);
            ah[mt][3] = *(const uint32_t*)(Ash + (r0 + 8) * 40 + c + 8);
            al[mt][0] = *(const uint32_t*)(Asl + r0 * 40 + c);
            al[mt][1] = *(const uint32_t*)(Asl + (r0 + 8) * 40 + c);
            al[mt][2] = *(const uint32_t*)(Asl + r0 * 40 + c + 8);
            al[mt][3] = *(const uint32_t*)(Asl + (r0 + 8) * 40 + c + 8);
        }
        #pragma unroll
        for (int nt = 0; nt < 4; nt++) {
            int n = wn * 32 + nt * 8 + gid;
            bh[nt][0] = *(const uint32_t*)(Bsh + n * 40 + c);
            bh[nt][1] = *(const uint32_t*)(Bsh + n * 40 + c + 8);
            bl[nt][0] = *(const uint32_t*)(Bsl + n * 40 + c);
            bl[nt][1] = *(const uint32_t*)(Bsl + n * 40 + c + 8);
        }
        #pragma unroll
        for (int mt = 0; mt < 2; mt++)
            #pragma unroll
            for (int nt = 0; nt < 4; nt++) {
                mma16816(acc[mt][nt], ah[mt][0], ah[mt][1], ah[mt][2], ah[mt][3], bh[nt][0], bh[nt][1]);
                mma16816(acc[mt][nt], ah[mt][0], ah[mt][1], ah[mt][2], ah[mt][3], bl[nt][0], bl[nt][1]);
                mma16816(acc[mt][nt], al[mt][0], al[mt][1], al[mt][2], al[mt][3], bh[nt][0], bh[nt][1]);
            }
    }
}

#define GEMM_PROLOG \
    __shared__ __half Ash[128*40], Asl[128*40], Bsh[64*40], Bsl[64*40]; \
    int tid = threadIdx.x; \
    int w = tid >> 5, gid = (tid & 31) >> 2, tig = tid & 3; \
    int wm = w >> 1, wn = w & 1; \
    float acc[2][4][4]; \
    _Pragma("unroll") for (int i = 0; i < 2; i++) \
    _Pragma("unroll") for (int j = 0; j < 4; j++) \
    _Pragma("unroll") for (int t = 0; t < 4; t++) acc[i][j][t] = 0.f;

// ---------------- conv-as-GEMM: M=4096, K=4096, N=256 ----------------
__global__ void __launch_bounds__(256) k_conv_mma(const float* __restrict__ srb) {
    GEMM_PROLOG
    int n0 = blockIdx.x * 64, m0 = blockIdx.y * 128;
    for (int k0 = 0; k0 < KCONV; k0 += 32) {
        __syncthreads();
        int p = k0 >> 8, cib = k0 & 255;
        int kh = p >> 2, kw = p & 3;
        #pragma unroll
        for (int i = 0; i < 8; i++) {
            int l = tid + i * 256;
            int m = l >> 4, kp = l & 15;
            int mm = m0 + m;
            int b = mm >> 10, rem = mm & 1023, oh = rem >> 5, ow = rem & 31;
            size_t g = ((size_t)(b * NTOT + (oh * 4 + kh) * 128 + ow * 4 + kw)) * CC + cib + kp * 2;
            ((uint32_t*)Ash)[m * 20 + kp] = *(const uint32_t*)(g_xh + g);
            ((uint32_t*)Asl)[m * 20 + kp] = *(const uint32_t*)(g_xl + g);
        }
        #pragma unroll
        for (int i = 0; i < 8; i++) {
            int l = tid + i * 256;
            int kk = l >> 6, n = l & 63;
            size_t g = (size_t)(k0 + kk) * CC + n0 + n;
            Bsh[n * 40 + kk] = g_wsrh[g];
            Bsl[n * 40 + kk] = g_wsrl[g];
        }
        __syncthreads();
        mma_step32(Ash, Asl, Bsh, Bsl, acc, wm, wn, gid, tig);
    }
    #pragma unroll
    for (int mt = 0; mt < 2; mt++)
        #pragma unroll
        for (int nt = 0; nt < 4; nt++) {
            int r0 = m0 + wm * 32 + mt * 16 + gid;
            int cb = n0 + wn * 32 + nt * 8 + tig * 2;
            g_xr[(size_t)r0 * CC + cb]       = acc[mt][nt][0] + srb[cb];
            g_xr[(size_t)r0 * CC + cb + 1]   = acc[mt][nt][1] + srb[cb + 1];
            g_xr[(size_t)(r0+8) * CC + cb]   = acc[mt][nt][2] + srb[cb];
            g_xr[(size_t)(r0+8) * CC + cb+1] = acc[mt][nt][3] + srb[cb + 1];
        }
}

// ---------------- LayerNorm (fp32, in place on g_xr) ----------------
__global__ void __launch_bounds__(256) k_layernorm(const float* __restrict__ gamma,
                                                   const float* __restrict__ beta) {
    int row  = blockIdx.x * 8 + (threadIdx.x >> 5);
    int lane = threadIdx.x & 31;
    float* xr = g_xr + (size_t)row * CC;
    float v[8], s = 0.f;
    #pragma unroll
    for (int i = 0; i < 8; i++) { v[i] = xr[lane + i * 32]; s += v[i]; }
    #pragma unroll
    for (int o = 16; o; o >>= 1) s += __shfl_xor_sync(0xffffffffu, s, o);
    float mu = s * (1.f / 256.f), s2 = 0.f;
    #pragma unroll
    for (int i = 0; i < 8; i++) { float d = v[i] - mu; s2 += d * d; }
    #pragma unroll
    for (int o = 16; o; o >>= 1) s2 += __shfl_xor_sync(0xffffffffu, s2, o);
    float rstd = rsqrtf(s2 * (1.f / 256.f) + 1e-5f);
    #pragma unroll
    for (int i = 0; i < 8; i++) {
        int c = lane + i * 32;
        xr[c] = (v[i] - mu) * rstd * gamma[c] + beta[c];
    }
}

// ---------------- KV projection: M=4096, K=256, N=512, scatter to fp16 K/V ----------------
__global__ void __launch_bounds__(256) k_kv_mma() {
    GEMM_PROLOG
    int n0 = blockIdx.x * 64, m0 = blockIdx.y * 128;
    for (int k0 = 0; k0 < CC; k0 += 32) {
        __syncthreads();
        load_A(g_xrh, g_xrl, CC, m0, k0, Ash, Asl);
        load_B(g_wkvh, g_wkvl, 2 * CC, k0, n0, Bsh, Bsl);
        __syncthreads();
        mma_step32(Ash, Asl, Bsh, Bsl, acc, wm, wn, gid, tig);
    }
    #pragma unroll
    for (int mt = 0; mt < 2; mt++)
        #pragma unroll
        for (int nt = 0; nt < 4; nt++)
            #pragma unroll
            for (int e = 0; e < 4; e++) {
                int r = m0 + wm * 32 + mt * 16 + gid + (e >= 2 ? 8 : 0);
                int n = n0 + wn * 32 + nt * 8 + tig * 2 + (e & 1);
                int b = r >> 10, pos = r & 1023;
                int half = n >> 8, hh = (n >> 5) & 7, d = n & 31;
                size_t dst = ((size_t)((b * NHH + hh) * NKV + pos)) * HDD + d;
                __half v = __float2half_rn(acc[mt][nt][e]);
                if (half == 0) g_kh[dst] = v; else g_vh[dst] = v;
            }
}

// ---------------- Q projection: M=16384, K=256, N=256 -> fp16 ----------------
__global__ void __launch_bounds__(256) k_qproj_mma(void) {
    GEMM_PROLOG
    int n0 = blockIdx.x * 64, m0 = blockIdx.y * 128;
    for (int k0 = 0; k0 < CC; k0 += 32) {
        __syncthreads();
        load_A(g_qih, g_qil, CC, m0, k0, Ash, Asl);
        load_B(g_wqh, g_wql, CC, k0, n0, Bsh, Bsl);
        __syncthreads();
        mma_step32(Ash, Asl, Bsh, Bsl, acc, wm, wn, gid, tig);
    }
    #pragma unroll
    for (int mt = 0; mt < 2; mt++)
        #pragma unroll
        for (int nt = 0; nt < 4; nt++)
            #pragma unroll
            for (int e = 0; e < 4; e++) {
                int r = m0 + wm * 32 + mt * 16 + gid + (e >= 2 ? 8 : 0);
                int n = n0 + wn * 32 + nt * 8 + tig * 2 + (e & 1);
                g_qhh[(size_t)r * CC + n] = __float2half_rn(acc[mt][nt][e]);
            }
}

// ---------------- Output projection: M=16384, K=256, N=256 -> d_out fp32 ----------------
__global__ void __launch_bounds__(256) k_proj_mma(const float* __restrict__ bp,
                                                  float* __restrict__ out) {
    GEMM_PROLOG
    int n0 = blockIdx.x * 64, m0 = blockIdx.y * 128;
    for (int k0 = 0; k0 < CC; k0 += 32) {
        __syncthreads();
        load_A(g_oh, g_ol, CC, m0, k0, Ash, Asl);
        load_B(g_pwh, g_pwl, CC, k0, n0, Bsh, Bsl);
        __syncthreads();
        mma_step32(Ash, Asl, Bsh, Bsl, acc, wm, wn, gid, tig);
    }
    #pragma unroll
    for (int mt = 0; mt < 2; mt++)
        #pragma unroll
        for (int nt = 0; nt < 4; nt++)
            #pragma unroll
            for (int e = 0; e < 4; e++) {
                int r = m0 + wm * 32 + mt * 16 + gid + (e >= 2 ? 8 : 0);
                int n = n0 + wn * 32 + nt * 8 + tig * 2 + (e & 1);
                out[(size_t)r * CC + n] = acc[mt][nt][e] + bp[n];
            }
}

// ---------------- Attention: 32 queries x 1024 keys, mma ----------------
#define ATT_S_BYTES   131072
#define ATT_P_BYTES   66048
#define ATT_Q_BYTES   2560
#define ATT_SMEM (ATT_S_BYTES + ATT_P_BYTES + ATT_Q_BYTES + 128)

__global__ void __launch_bounds__(256) k_attn(const int* __restrict__ qlen) {
    extern __shared__ unsigned char smraw[];
    float*  S    = (float*)smraw;
    __half* P    = (__half*)(smraw + ATT_S_BYTES);
    __half* Qs   = (__half*)(smraw + ATT_S_BYTES + ATT_P_BYTES);
    float*  linv = (float*)(smraw + ATT_S_BYTES + ATT_P_BYTES + ATT_Q_BYTES);
    float*  Ored = S;   // reused after softmax

    int tid = threadIdx.x;
    int h = blockIdx.y;
    int q0 = blockIdx.x * 32;

    int l0 = qlen[0], l1 = qlen[1], l2 = qlen[2];
    int b = 0;
    if (q0 >= l0) b = 1;
    if (q0 >= l0 + l1) b = 2;
    if (q0 >= l0 + l1 + l2) b = 3;

    const __half* Kb = g_kh + ((size_t)(b * NHH + h) * NKV) * HDD;
    const __half* Vb = g_vh + ((size_t)(b * NHH + h) * NKV) * HDD;

    // stage Q [32 rows][32 d] -> Qs stride 40
    #pragma unroll
    for (int i = 0; i < 2; i++) {
        int l = tid + i * 256;
        int r = l >> 4, dp = l & 15;
        ((uint32_t*)Qs)[r * 20 + dp] =
            *(const uint32_t*)(g_qhh + (size_t)(q0 + r) * CC + h * HDD + dp * 2);
    }
    __syncthreads();

    int w = tid >> 5, gid = (tid & 31) >> 2, tig = tid & 3;

    // ---- QK: warp w computes S[:, w*128 .. w*128+128) ----
    for (int cch = 0; cch < 4; cch++) {
        int kb = w * 128 + cch * 32;
        float acc[2][4][4];
        #pragma unroll
        for (int i = 0; i < 2; i++)
            #pragma unroll
            for (int j = 0; j < 4; j++)
                #pragma unroll
                for (int t = 0; t < 4; t++) acc[i][j][t] = 0.f;
        #pragma unroll
        for (int ks = 0; ks < 32; ks += 16) {
            int c = ks + tig * 2;
            uint32_t a[2][4], bq[4][2];
            #pragma unroll
            for (int mt = 0; mt < 2; mt++) {
                int r0 = mt * 16 + gid;
                a[mt][0] = *(const uint32_t*)(Qs + r0 * 40 + c);
                a[mt][1] = *(const uint32_t*)(Qs + (r0 + 8) * 40 + c);
                a[mt][2] = *(const uint32_t*)(Qs + r0 * 40 + c + 8);
                a[mt][3] = *(const uint32_t*)(Qs + (r0 + 8) * 40 + c + 8);
            }
            #pragma unroll
            for (int nt = 0; nt < 4; nt++) {
                int key = kb + nt * 8 + gid;
                bq[nt][0] = *(const uint32_t*)(Kb + (size_t)key * HDD + c);
                bq[nt][1] = *(const uint32_t*)(Kb + (size_t)key * HDD + c + 8);
            }
            #pragma unroll
            for (int mt = 0; mt < 2; mt++)
                #pragma unroll
                for (int nt = 0; nt < 4; nt++)
                    mma16816(acc[mt][nt], a[mt][0], a[mt][1], a[mt][2], a[mt][3],
                             bq[nt][0], bq[nt][1]);
        }
        #pragma unroll
        for (int mt = 0; mt < 2; mt++)
            #pragma unroll
            for (int nt = 0; nt < 4; nt++) {
                int r0 = mt * 16 + gid;
                int col = kb + nt * 8 + tig * 2;
                S[r0 * 1024 + col]           = acc[mt][nt][0];
                S[r0 * 1024 + col + 1]       = acc[mt][nt][1];
                S[(r0 + 8) * 1024 + col]     = acc[mt][nt][2];
                S[(r0 + 8) * 1024 + col + 1] = acc[mt][nt][3];
            }
    }
    __syncthreads();

    // ---- softmax rows w*4..w*4+3 -> P fp16 (unnormalized) ----
    int lane = tid & 31;
    for (int rr = 0; rr < 4; rr++) {
        int r = w * 4 + rr;
        float* row = S + r * 1024;
        __half* prow = P + r * 1032;
        float m = -1e30f;
        for (int j = lane; j < 1024; j += 32) m = fmaxf(m, row[j]);
        #pragma unroll
        for (int o = 16; o; o >>= 1) m = fmaxf(m, __shfl_xor_sync(0xffffffffu, m, o));
        float s = 0.f;
        for (int j = lane; j < 1024; j += 32) {
            float p = __expf((row[j] - m) * SCALE);
            prow[j] = __float2half_rn(p);
            s += p;
        }
        #pragma unroll
        for (int o = 16; o; o >>= 1) s += __shfl_xor_sync(0xffffffffu, s, o);
        if (lane == 0) linv[r] = 1.f / s;
    }
    __syncthreads();

    // ---- PV: warp w handles keys [w*128, w*128+128) ----
    {
        float acc[2][4][4];
        #pragma unroll
        for (int i = 0; i < 2; i++)
            #pragma unroll
            for (int j = 0; j < 4; j++)
                #pragma unroll
                for (int t = 0; t < 4; t++) acc[i][j][t] = 0.f;
        int kb = w * 128;
        for (int ks = 0; ks < 128; ks += 16) {
            int c = kb + ks + tig * 2;
            uint32_t a[2][4], bv[4][2];
            #pragma unroll
            for (int mt = 0; mt < 2; mt++) {
                int r0 = mt * 16 + gid;
                a[mt][0] = *(const uint32_t*)(P + r0 * 1032 + c);
                a[mt][1] = *(const uint32_t*)(P + (r0 + 8) * 1032 + c);
                a[mt][2] = *(const uint32_t*)(P + r0 * 1032 + c + 8);
                a[mt][3] = *(const uint32_t*)(P + (r0 + 8) * 1032 + c + 8);
            }
            #pragma unroll
            for (int nt = 0; nt < 4; nt++) {
                int n = nt * 8 + gid;
                bv[nt][0] = pack2(Vb[(size_t)c * HDD + n], Vb[(size_t)(c + 1) * HDD + n]);
                bv[nt][1] = pack2(Vb[(size_t)(c + 8) * HDD + n], Vb[(size_t)(c + 9) * HDD + n]);
            }
            #pragma unroll
            for (int mt = 0; mt < 2; mt++)
                #pragma unroll
                for (int nt = 0; nt < 4; nt++)
                    mma16816(acc[mt][nt], a[mt][0], a[mt][1], a[mt][2], a[mt][3],
                             bv[nt][0], bv[nt][1]);
        }
        #pragma unroll
        for (int mt = 0; mt < 2; mt++)
            #pragma unroll
            for (int nt = 0; nt < 4; nt++) {
                int r0 = mt * 16 + gid;
                int col = nt * 8 + tig * 2;
                Ored[w * 1056 + r0 * 33 + col]           = acc[mt][nt][0];
                Ored[w * 1056 + r0 * 33 + col + 1]       = acc[mt][nt][1];
                Ored[w * 1056 + (r0 + 8) * 33 + col]     = acc[mt][nt][2];
                Ored[w * 1056 + (r0 + 8) * 33 + col + 1] = acc[mt][nt][3];
            }
    }
    __syncthreads();

    // ---- reduce 8 partials, scale, split-write ----
    #pragma unroll
    for (int i = 0; i < 4; i++) {
        int e = tid + i * 256;
        int r = e >> 5, d = e & 31;
        float s = 0.f;
        #pragma unroll
        for (int w2 = 0; w2 < 8; w2++) s += Ored[w2 * 1056 + r * 33 + d];
        s *= linv[r];
        __half hh, ll; fsplit(s, hh, ll);
        size_t dst = (size_t)(q0 + r) * CC + h * HDD + d;
        g_oh[dst] = hh;
        g_ol[dst] = ll;
    }
}

// ---------------- launch ----------------
extern "C" void kernel_launch(void* const* d_in, const int* in_sizes, int n_in,
                              void* d_out, int out_size) {
    const float* x      = (const float*)d_in[0];
    const float* q      = (const float*)d_in[1];
    const int*   qlen   = (const int*)  d_in[4];
    const float* w_q    = (const float*)d_in[5];
    const float* w_kv   = (const float*)d_in[6];
    const float* sr_w   = (const float*)d_in[7];
    const float* sr_b   = (const float*)d_in[8];
    const float* ln_g   = (const float*)d_in[9];
    const float* ln_b   = (const float*)d_in[10];
    const float* proj_w = (const float*)d_in[11];
    const float* proj_b = (const float*)d_in[12];
    float* out = (float*)d_out;

    cudaFuncSetAttribute(k_attn, cudaFuncAttributeMaxDynamicSharedMemorySize, ATT_SMEM);

    __half *xh, *xl, *qih, *qil, *wqh, *wql, *wkvh, *wkvl, *pwh, *pwl, *xrh, *xrl;
    cudaGetSymbolAddress((void**)&xh,  g_xh);  cudaGetSymbolAddress((void**)&xl,  g_xl);
    cudaGetSymbolAddress((void**)&qih, g_qih); cudaGetSymbolAddress((void**)&qil, g_qil);
    cudaGetSymbolAddress((void**)&wqh, g_wqh); cudaGetSymbolAddress((void**)&wql, g_wql);
    cudaGetSymbolAddress((void**)&wkvh,g_wkvh);cudaGetSymbolAddress((void**)&wkvl,g_wkvl);
    cudaGetSymbolAddress((void**)&pwh, g_pwh); cudaGetSymbolAddress((void**)&pwl, g_pwl);
    cudaGetSymbolAddress((void**)&xrh, g_xrh); cudaGetSymbolAddress((void**)&xrl, g_xrl);
    float* xr; cudaGetSymbolAddress((void**)&xr, g_xr);

    k_split<<<(BB*NTOT*CC + 255)/256, 256>>>(x, xh, xl, BB*NTOT*CC);   // FULL x!
    k_split<<<(TQ*CC + 255)/256, 256>>>(q, qih, qil, TQ*CC);
    k_split<<<(CC*CC + 255)/256, 256>>>(w_q, wqh, wql, CC*CC);
    k_split<<<(CC*2*CC + 255)/256, 256>>>(w_kv, wkvh, wkvl, CC*2*CC);
    k_split<<<(CC*CC + 255)/256, 256>>>(proj_w, pwh, pwl, CC*CC);
    k_split_srw<<<(KCONV*CC + 255)/256, 256>>>(sr_w);

    k_conv_mma<<<dim3(CC/64, (BB*NKV)/128), 256>>>(sr_b);
    k_layernorm<<<(BB*NKV)/8, 256>>>(ln_g, ln_b);
    k_split<<<(BB*NKV*CC + 255)/256, 256>>>(xr, xrh, xrl, BB*NKV*CC);
    k_kv_mma<<<dim3((2*CC)/64, (BB*NKV)/128), 256>>>();
    k_qproj_mma<<<dim3(CC/64, TQ/128), 256>>>();
    k_attn<<<dim3(TQ/32, NHH), 256, ATT_SMEM>>>(qlen);
    k_proj_mma<<<dim3(CC/64, TQ/128), 256>>>(proj_b, out);
}

// round 6
// speedup vs baseline: 3.7103x; 1.8745x over previous
#include <cuda_runtime.h>
#include <cuda_fp16.h>
#include <math.h>
#include <stdint.h>

#define BB    4
#define NTOT  16384
#define CC    256
#define NHH   8
#define HDD   32
#define NKV   1024
#define KCONV 4096
#define TQ    16384
#define SCALE 0.17677669529663689f
#define C2E   0.25503486963f   // SCALE * log2(e)  (fixed)

// ---------------- scratch (device globals) ----------------
__device__ __half g_wqh[CC*CC],   g_wql[CC*CC];
__device__ __half g_wkvh[CC*2*CC],g_wkvl[CC*2*CC];
__device__ __half g_pwh[CC*CC],   g_pwl[CC*CC];
__device__ __half g_wsrh[KCONV*CC], g_wsrl[KCONV*CC];
__device__ float  g_xr [BB*NKV*CC];                       // conv out, LN in place
__device__ __half g_kh [BB*NHH*NKV*HDD], g_vh[BB*NHH*NKV*HDD]; // [b][h][pos][d]
__device__ __half g_qhh[TQ*CC];                           // projected q fp16
__device__ float  g_o  [TQ*CC];                           // attention out fp32

// ---------------- helpers ----------------
__device__ __forceinline__ void fsplit(float x, __half& h, __half& l) {
    h = __float2half_rn(x);
    l = __float2half_rn(x - __half2float(h));
}

__device__ __forceinline__ void mma16816(float* c,
    uint32_t a0, uint32_t a1, uint32_t a2, uint32_t a3, uint32_t b0, uint32_t b1) {
    asm volatile("mma.sync.aligned.m16n8k16.row.col.f32.f16.f16.f32 "
        "{%0,%1,%2,%3}, {%4,%5,%6,%7}, {%8,%9}, {%0,%1,%2,%3};\n"
        : "+f"(c[0]), "+f"(c[1]), "+f"(c[2]), "+f"(c[3])
        : "r"(a0), "r"(a1), "r"(a2), "r"(a3), "r"(b0), "r"(b1));
}

__device__ __forceinline__ uint32_t pack2(__half lo, __half hi) {
    __half2 t = __halves2half2(lo, hi);
    return *(uint32_t*)&t;
}

// ---------------- weight split kernels ----------------
__global__ void k_split(const float* __restrict__ src, __half* __restrict__ dh,
                        __half* __restrict__ dl, int n) {
    int i = blockIdx.x * 256 + threadIdx.x;
    if (i < n) { __half h, l; fsplit(src[i], h, l); dh[i] = h; dl[i] = l; }
}

__global__ void k_split_srw(const float* __restrict__ srw) {
    int idx = blockIdx.x * 256 + threadIdx.x;
    if (idx >= KCONV * CC) return;
    int co = idx & 255;
    int k  = idx >> 8;
    int ci = k & 255;
    int p  = k >> 8;
    float v = srw[(size_t)co * KCONV + ci * 16 + p];
    __half h, l; fsplit(v, h, l);
    g_wsrh[idx] = h; g_wsrl[idx] = l;
}

// ---------------- GEMM tile loaders (BM=128, BN=64, BK=32; stride 40 halves) ----------------
__device__ __forceinline__ void load_A_f32(const float* __restrict__ A,
                                           int K, int m0, int k0,
                                           __half* Ash, __half* Asl) {
    int tid = threadIdx.x;
    #pragma unroll
    for (int i = 0; i < 8; i++) {
        int l = tid + i * 256;
        int m = l >> 4, kp = l & 15;
        float2 v = *(const float2*)(A + (size_t)(m0 + m) * K + k0 + kp * 2);
        __half h0, l0, h1, l1;
        fsplit(v.x, h0, l0); fsplit(v.y, h1, l1);
        ((uint32_t*)Ash)[m * 20 + kp] = pack2(h0, h1);
        ((uint32_t*)Asl)[m * 20 + kp] = pack2(l0, l1);
    }
}

__device__ __forceinline__ void load_B(const __half* __restrict__ Bh, const __half* __restrict__ Bl,
                                       int N, int k0, int n0, __half* Bsh, __half* Bsl) {
    int tid = threadIdx.x;
    #pragma unroll
    for (int i = 0; i < 8; i++) {
        int l = tid + i * 256;
        int kk = l >> 6, n = l & 63;
        size_t g = (size_t)(k0 + kk) * N + n0 + n;
        Bsh[n * 40 + kk] = Bh[g];
        Bsl[n * 40 + kk] = Bl[g];
    }
}

// 3-mma split compute for one BK=32 step. warp tile 32x32 (2 m16 x 4 n8).
__device__ __forceinline__ void mma_step32(const __half* Ash, const __half* Asl,
                                           const __half* Bsh, const __half* Bsl,
                                           float acc[2][4][4], int wm, int wn,
                                           int gid, int tig) {
    #pragma unroll
    for (int ks = 0; ks < 32; ks += 16) {
        int c = ks + tig * 2;
        uint32_t ah[2][4], al[2][4], bh[4][2], bl[4][2];
        #pragma unroll
        for (int mt = 0; mt < 2; mt++) {
            int r0 = wm * 32 + mt * 16 + gid;
            ah[mt][0] = *(const uint32_t*)(Ash + r0 * 40 + c);
            ah[mt][1] = *(const uint32_t*)(Ash + (r0 + 8) * 40 + c);
            ah[mt][2] = *(const uint32_t*)(Ash + r0 * 40 + c + 8);
            ah[mt][3] = *(const uint32_t*)(Ash + (r0 + 8) * 40 + c + 8);
            al[mt][0] = *(const uint32_t*)(Asl + r0 * 40 + c);
            al[mt][1] = *(const uint32_t*)(Asl + (r0 + 8) * 40 + c);
            al[mt][2] = *(const uint32_t*)(Asl + r0 * 40 + c + 8);
            al[mt][3] = *(const uint32_t*)(Asl + (r0 + 8) * 40 + c + 8);
        }
        #pragma unroll
        for (int nt = 0; nt < 4; nt++) {
            int n = wn * 32 + nt * 8 + gid;
            bh[nt][0] = *(const uint32_t*)(Bsh + n * 40 + c);
            bh[nt][1] = *(const uint32_t*)(Bsh + n * 40 + c + 8);
            bl[nt][0] = *(const uint32_t*)(Bsl + n * 40 + c);
            bl[nt][1] = *(const uint32_t*)(Bsl + n * 40 + c + 8);
        }
        #pragma unroll
        for (int mt = 0; mt < 2; mt++)
            #pragma unroll
            for (int nt = 0; nt < 4; nt++) {
                mma16816(acc[mt][nt], ah[mt][0], ah[mt][1], ah[mt][2], ah[mt][3], bh[nt][0], bh[nt][1]);
                mma16816(acc[mt][nt], ah[mt][0], ah[mt][1], ah[mt][2], ah[mt][3], bl[nt][0], bl[nt][1]);
                mma16816(acc[mt][nt], al[mt][0], al[mt][1], al[mt][2], al[mt][3], bh[nt][0], bh[nt][1]);
            }
    }
}

#define GEMM_PROLOG \
    __shared__ __half Ash[128*40], Asl[128*40], Bsh[64*40], Bsl[64*40]; \
    int tid = threadIdx.x; \
    int w = tid >> 5, gid = (tid & 31) >> 2, tig = tid & 3; \
    int wm = w >> 1, wn = w & 1; \
    float acc[2][4][4]; \
    _Pragma("unroll") for (int i = 0; i < 2; i++) \
    _Pragma("unroll") for (int j = 0; j < 4; j++) \
    _Pragma("unroll") for (int t = 0; t < 4; t++) acc[i][j][t] = 0.f;

// ---------------- conv-as-GEMM: M=4096, K=4096, N=256 (x read fp32 inline) ----------------
__global__ void __launch_bounds__(256) k_conv_mma(const float* __restrict__ x,
                                                  const float* __restrict__ srb) {
    GEMM_PROLOG
    int n0 = blockIdx.x * 64, m0 = blockIdx.y * 128;
    for (int k0 = 0; k0 < KCONV; k0 += 32) {
        __syncthreads();
        int p = k0 >> 8, cib = k0 & 255;
        int kh = p >> 2, kw = p & 3;
        #pragma unroll
        for (int i = 0; i < 8; i++) {
            int l = tid + i * 256;
            int m = l >> 4, kp = l & 15;
            int mm = m0 + m;
            int b = mm >> 10, rem = mm & 1023, oh = rem >> 5, ow = rem & 31;
            size_t g = ((size_t)(b * NTOT + (oh * 4 + kh) * 128 + ow * 4 + kw)) * CC + cib + kp * 2;
            float2 v = *(const float2*)(x + g);
            __half h0, l0, h1, l1;
            fsplit(v.x, h0, l0); fsplit(v.y, h1, l1);
            ((uint32_t*)Ash)[m * 20 + kp] = pack2(h0, h1);
            ((uint32_t*)Asl)[m * 20 + kp] = pack2(l0, l1);
        }
        #pragma unroll
        for (int i = 0; i < 8; i++) {
            int l = tid + i * 256;
            int kk = l >> 6, n = l & 63;
            size_t g = (size_t)(k0 + kk) * CC + n0 + n;
            Bsh[n * 40 + kk] = g_wsrh[g];
            Bsl[n * 40 + kk] = g_wsrl[g];
        }
        __syncthreads();
        mma_step32(Ash, Asl, Bsh, Bsl, acc, wm, wn, gid, tig);
    }
    #pragma unroll
    for (int mt = 0; mt < 2; mt++)
        #pragma unroll
        for (int nt = 0; nt < 4; nt++) {
            int r0 = m0 + wm * 32 + mt * 16 + gid;
            int cb = n0 + wn * 32 + nt * 8 + tig * 2;
            g_xr[(size_t)r0 * CC + cb]       = acc[mt][nt][0] + srb[cb];
            g_xr[(size_t)r0 * CC + cb + 1]   = acc[mt][nt][1] + srb[cb + 1];
            g_xr[(size_t)(r0+8) * CC + cb]   = acc[mt][nt][2] + srb[cb];
            g_xr[(size_t)(r0+8) * CC + cb+1] = acc[mt][nt][3] + srb[cb + 1];
        }
}

// ---------------- LayerNorm (fp32, in place on g_xr) ----------------
__global__ void __launch_bounds__(256) k_layernorm(const float* __restrict__ gamma,
                                                   const float* __restrict__ beta) {
    int row  = blockIdx.x * 8 + (threadIdx.x >> 5);
    int lane = threadIdx.x & 31;
    float* xr = g_xr + (size_t)row * CC;
    float v[8], s = 0.f;
    #pragma unroll
    for (int i = 0; i < 8; i++) { v[i] = xr[lane + i * 32]; s += v[i]; }
    #pragma unroll
    for (int o = 16; o; o >>= 1) s += __shfl_xor_sync(0xffffffffu, s, o);
    float mu = s * (1.f / 256.f), s2 = 0.f;
    #pragma unroll
    for (int i = 0; i < 8; i++) { float d = v[i] - mu; s2 += d * d; }
    #pragma unroll
    for (int o = 16; o; o >>= 1) s2 += __shfl_xor_sync(0xffffffffu, s2, o);
    float rstd = rsqrtf(s2 * (1.f / 256.f) + 1e-5f);
    #pragma unroll
    for (int i = 0; i < 8; i++) {
        int c = lane + i * 32;
        xr[c] = (v[i] - mu) * rstd * gamma[c] + beta[c];
    }
}

// ---------------- KV projection: M=4096, K=256, N=512, scatter to fp16 K/V ----------------
__global__ void __launch_bounds__(256) k_kv_mma() {
    GEMM_PROLOG
    int n0 = blockIdx.x * 64, m0 = blockIdx.y * 128;
    for (int k0 = 0; k0 < CC; k0 += 32) {
        __syncthreads();
        load_A_f32(g_xr, CC, m0, k0, Ash, Asl);
        load_B(g_wkvh, g_wkvl, 2 * CC, k0, n0, Bsh, Bsl);
        __syncthreads();
        mma_step32(Ash, Asl, Bsh, Bsl, acc, wm, wn, gid, tig);
    }
    #pragma unroll
    for (int mt = 0; mt < 2; mt++)
        #pragma unroll
        for (int nt = 0; nt < 4; nt++)
            #pragma unroll
            for (int e = 0; e < 4; e++) {
                int r = m0 + wm * 32 + mt * 16 + gid + (e >= 2 ? 8 : 0);
                int n = n0 + wn * 32 + nt * 8 + tig * 2 + (e & 1);
                int b = r >> 10, pos = r & 1023;
                int half = n >> 8, hh = (n >> 5) & 7, d = n & 31;
                size_t dst = ((size_t)((b * NHH + hh) * NKV + pos)) * HDD + d;
                __half v = __float2half_rn(acc[mt][nt][e]);
                if (half == 0) g_kh[dst] = v; else g_vh[dst] = v;
            }
}

// ---------------- Q projection: M=16384, K=256, N=256 -> fp16 ----------------
__global__ void __launch_bounds__(256) k_qproj_mma(const float* __restrict__ q) {
    GEMM_PROLOG
    int n0 = blockIdx.x * 64, m0 = blockIdx.y * 128;
    for (int k0 = 0; k0 < CC; k0 += 32) {
        __syncthreads();
        load_A_f32(q, CC, m0, k0, Ash, Asl);
        load_B(g_wqh, g_wql, CC, k0, n0, Bsh, Bsl);
        __syncthreads();
        mma_step32(Ash, Asl, Bsh, Bsl, acc, wm, wn, gid, tig);
    }
    #pragma unroll
    for (int mt = 0; mt < 2; mt++)
        #pragma unroll
        for (int nt = 0; nt < 4; nt++)
            #pragma unroll
            for (int e = 0; e < 4; e++) {
                int r = m0 + wm * 32 + mt * 16 + gid + (e >= 2 ? 8 : 0);
                int n = n0 + wn * 32 + nt * 8 + tig * 2 + (e & 1);
                g_qhh[(size_t)r * CC + n] = __float2half_rn(acc[mt][nt][e]);
            }
}

// ---------------- Output projection: M=16384, K=256, N=256 -> d_out fp32 ----------------
__global__ void __launch_bounds__(256) k_proj_mma(const float* __restrict__ bp,
                                                  float* __restrict__ out) {
    GEMM_PROLOG
    int n0 = blockIdx.x * 64, m0 = blockIdx.y * 128;
    for (int k0 = 0; k0 < CC; k0 += 32) {
        __syncthreads();
        load_A_f32(g_o, CC, m0, k0, Ash, Asl);
        load_B(g_pwh, g_pwl, CC, k0, n0, Bsh, Bsl);
        __syncthreads();
        mma_step32(Ash, Asl, Bsh, Bsl, acc, wm, wn, gid, tig);
    }
    #pragma unroll
    for (int mt = 0; mt < 2; mt++)
        #pragma unroll
        for (int nt = 0; nt < 4; nt++)
            #pragma unroll
            for (int e = 0; e < 4; e++) {
                int r = m0 + wm * 32 + mt * 16 + gid + (e >= 2 ? 8 : 0);
                int n = n0 + wn * 32 + nt * 8 + tig * 2 + (e & 1);
                out[(size_t)r * CC + n] = acc[mt][nt][e] + bp[n];
            }
}

// ---------------- Flash attention: 128 queries/block, online softmax ----------------
#define VT_S 130

__global__ void __launch_bounds__(256) k_attn_flash(const int* __restrict__ qlen) {
    __shared__ __half Ks[128 * 40];
    __shared__ __half Vt[32 * VT_S];

    int tid = threadIdx.x;
    int w = tid >> 5, lane = tid & 31;
    int gid = lane >> 2, tig = lane & 3;
    int h = blockIdx.y;
    int q0 = blockIdx.x * 128;

    int l0 = qlen[0], l1 = qlen[1], l2 = qlen[2];
    int b = 0;
    if (q0 >= l0) b = 1;
    if (q0 >= l0 + l1) b = 2;
    if (q0 >= l0 + l1 + l2) b = 3;

    const __half* Kb = g_kh + ((size_t)(b * NHH + h) * NKV) * HDD;
    const __half* Vb = g_vh + ((size_t)(b * NHH + h) * NKV) * HDD;

    // Q fragments (loop-invariant)
    uint32_t aQ[2][4];
    {
        const __half* Qp = g_qhh + (size_t)(q0 + w * 16) * CC + h * HDD;
        #pragma unroll
        for (int kc = 0; kc < 2; kc++) {
            int c = kc * 16 + tig * 2;
            aQ[kc][0] = *(const uint32_t*)(Qp + (size_t)gid * CC + c);
            aQ[kc][1] = *(const uint32_t*)(Qp + (size_t)(gid + 8) * CC + c);
            aQ[kc][2] = *(const uint32_t*)(Qp + (size_t)gid * CC + c + 8);
            aQ[kc][3] = *(const uint32_t*)(Qp + (size_t)(gid + 8) * CC + c + 8);
        }
    }

    float o[4][4];
    #pragma unroll
    for (int i = 0; i < 4; i++)
        #pragma unroll
        for (int j = 0; j < 4; j++) o[i][j] = 0.f;
    float mrow[2] = {-1e30f, -1e30f};
    float lsum[2] = {0.f, 0.f};

    for (int kt = 0; kt < 8; kt++) {
        #pragma unroll
        for (int i = 0; i < 8; i++) {
            int idx = tid + i * 256;
            int key = idx >> 4, dp = idx & 15;
            ((uint32_t*)Ks)[key * 20 + dp] =
                *(const uint32_t*)(Kb + (size_t)(kt * 128 + key) * HDD + dp * 2);
        }
        #pragma unroll
        for (int i = 0; i < 8; i++) {
            int idx = tid + i * 256;
            int key = idx >> 4, dp = idx & 15;
            uint32_t u = *(const uint32_t*)(Vb + (size_t)(kt * 128 + key) * HDD + dp * 2);
            __half2 h2 = *(__half2*)&u;
            Vt[(dp * 2) * VT_S + key]     = __low2half(h2);
            Vt[(dp * 2 + 1) * VT_S + key] = __high2half(h2);
        }
        __syncthreads();

        // ---- S = Q K^T ----
        float c[16][4];
        #pragma unroll
        for (int t = 0; t < 16; t++) {
            c[t][0] = c[t][1] = c[t][2] = c[t][3] = 0.f;
            #pragma unroll
            for (int kc = 0; kc < 2; kc++) {
                int cc = kc * 16 + tig * 2;
                uint32_t b0 = *(const uint32_t*)(Ks + (t * 8 + gid) * 40 + cc);
                uint32_t b1 = *(const uint32_t*)(Ks + (t * 8 + gid) * 40 + cc + 8);
                mma16816(c[t], aQ[kc][0], aQ[kc][1], aQ[kc][2], aQ[kc][3], b0, b1);
            }
        }

        // ---- online softmax ----
        float tm0 = -1e30f, tm1 = -1e30f;
        #pragma unroll
        for (int t = 0; t < 16; t++) {
            tm0 = fmaxf(tm0, fmaxf(c[t][0], c[t][1]));
            tm1 = fmaxf(tm1, fmaxf(c[t][2], c[t][3]));
        }
        tm0 = fmaxf(tm0, __shfl_xor_sync(0xffffffffu, tm0, 1));
        tm0 = fmaxf(tm0, __shfl_xor_sync(0xffffffffu, tm0, 2));
        tm1 = fmaxf(tm1, __shfl_xor_sync(0xffffffffu, tm1, 1));
        tm1 = fmaxf(tm1, __shfl_xor_sync(0xffffffffu, tm1, 2));
        float mn0 = fmaxf(mrow[0], tm0);
        float mn1 = fmaxf(mrow[1], tm1);
        float f0 = exp2f((mrow[0] - mn0) * C2E);
        float f1 = exp2f((mrow[1] - mn1) * C2E);
        mrow[0] = mn0; mrow[1] = mn1;
        lsum[0] *= f0; lsum[1] *= f1;
        #pragma unroll
        for (int nt = 0; nt < 4; nt++) {
            o[nt][0] *= f0; o[nt][1] *= f0;
            o[nt][2] *= f1; o[nt][3] *= f1;
        }
        float ps0 = 0.f, ps1 = 0.f;
        uint32_t pf[16][2];
        #pragma unroll
        for (int t = 0; t < 16; t++) {
            float p0 = exp2f((c[t][0] - mn0) * C2E);
            float p1 = exp2f((c[t][1] - mn0) * C2E);
            float p2 = exp2f((c[t][2] - mn1) * C2E);
            float p3 = exp2f((c[t][3] - mn1) * C2E);
            ps0 += p0 + p1;
            ps1 += p2 + p3;
            pf[t][0] = pack2(__float2half_rn(p0), __float2half_rn(p1));
            pf[t][1] = pack2(__float2half_rn(p2), __float2half_rn(p3));
        }
        lsum[0] += ps0;
        lsum[1] += ps1;

        // ---- O += P V ----
        #pragma unroll
        for (int j = 0; j < 8; j++) {
            uint32_t a0 = pf[2 * j][0];
            uint32_t a1 = pf[2 * j][1];
            uint32_t a2 = pf[2 * j + 1][0];
            uint32_t a3 = pf[2 * j + 1][1];
            #pragma unroll
            for (int nt = 0; nt < 4; nt++) {
                int d = nt * 8 + gid;
                uint32_t b0 = *(const uint32_t*)(Vt + d * VT_S + 16 * j + tig * 2);
                uint32_t b1 = *(const uint32_t*)(Vt + d * VT_S + 16 * j + tig * 2 + 8);
                mma16816(o[nt], a0, a1, a2, a3, b0, b1);
            }
        }
        __syncthreads();
    }

    // ---- FIX: reduce lsum across the 4 lanes of each quad (rows span tig 0..3) ----
    lsum[0] += __shfl_xor_sync(0xffffffffu, lsum[0], 1);
    lsum[0] += __shfl_xor_sync(0xffffffffu, lsum[0], 2);
    lsum[1] += __shfl_xor_sync(0xffffffffu, lsum[1], 1);
    lsum[1] += __shfl_xor_sync(0xffffffffu, lsum[1], 2);

    // ---- normalize + write fp32 ----
    float i0 = 1.f / lsum[0], i1 = 1.f / lsum[1];
    float* Op = g_o + (size_t)(q0 + w * 16) * CC + h * HDD;
    #pragma unroll
    for (int nt = 0; nt < 4; nt++) {
        int col = nt * 8 + tig * 2;
        float2 v0 = make_float2(o[nt][0] * i0, o[nt][1] * i0);
        float2 v1 = make_float2(o[nt][2] * i1, o[nt][3] * i1);
        *(float2*)(Op + (size_t)gid * CC + col)       = v0;
        *(float2*)(Op + (size_t)(gid + 8) * CC + col) = v1;
    }
}

// ---------------- launch ----------------
extern "C" void kernel_launch(void* const* d_in, const int* in_sizes, int n_in,
                              void* d_out, int out_size) {
    const float* x      = (const float*)d_in[0];
    const float* q      = (const float*)d_in[1];
    const int*   qlen   = (const int*)  d_in[4];
    const float* w_q    = (const float*)d_in[5];
    const float* w_kv   = (const float*)d_in[6];
    const float* sr_w   = (const float*)d_in[7];
    const float* sr_b   = (const float*)d_in[8];
    const float* ln_g   = (const float*)d_in[9];
    const float* ln_b   = (const float*)d_in[10];
    const float* proj_w = (const float*)d_in[11];
    const float* proj_b = (const float*)d_in[12];
    float* out = (float*)d_out;

    __half *wqh, *wql, *wkvh, *wkvl, *pwh, *pwl;
    cudaGetSymbolAddress((void**)&wqh, g_wqh); cudaGetSymbolAddress((void**)&wql, g_wql);
    cudaGetSymbolAddress((void**)&wkvh,g_wkvh);cudaGetSymbolAddress((void**)&wkvl,g_wkvl);
    cudaGetSymbolAddress((void**)&pwh, g_pwh); cudaGetSymbolAddress((void**)&pwl, g_pwl);

    k_split<<<(CC*CC + 255)/256, 256>>>(w_q, wqh, wql, CC*CC);
    k_split<<<(CC*2*CC + 255)/256, 256>>>(w_kv, wkvh, wkvl, CC*2*CC);
    k_split<<<(CC*CC + 255)/256, 256>>>(proj_w, pwh, pwl, CC*CC);
    k_split_srw<<<(KCONV*CC + 255)/256, 256>>>(sr_w);

    k_conv_mma<<<dim3(CC/64, (BB*NKV)/128), 256>>>(x, sr_b);
    k_layernorm<<<(BB*NKV)/8, 256>>>(ln_g, ln_b);
    k_kv_mma<<<dim3((2*CC)/64, (BB*NKV)/128), 256>>>();
    k_qproj_mma<<<dim3(CC/64, TQ/128), 256>>>(q);
    k_attn_flash<<<dim3(TQ/128, NHH), 256>>>(qlen);
    k_proj_mma<<<dim3(CC/64, TQ/128), 256>>>(proj_b, out);
}

// round 8
// speedup vs baseline: 4.3259x; 1.1659x over previous
#include <cuda_runtime.h>
#include <cuda_fp16.h>
#include <math.h>
#include <stdint.h>

#define BB    4
#define NTOT  16384
#define CC    256
#define NHH   8
#define HDD   32
#define NKV   1024
#define KCONV 4096
#define TQ    16384
#define SCALE 0.17677669529663689f
#define C2E   0.25503486963f   // SCALE * log2(e)

// ---------------- scratch (device globals) ----------------
__device__ __half g_wqh[CC*CC],   g_wql[CC*CC];
__device__ __half g_wkvh[CC*2*CC],g_wkvl[CC*2*CC];
__device__ __half g_pwh[CC*CC],   g_pwl[CC*CC];
__device__ __half g_wsrh[KCONV*CC], g_wsrl[KCONV*CC];
__device__ float  g_xr [BB*NKV*CC];
__device__ __half g_kh [BB*NHH*NKV*HDD], g_vh[BB*NHH*NKV*HDD];
__device__ __half g_qhh[TQ*CC];
__device__ float  g_o  [TQ*CC];

// ---------------- helpers ----------------
__device__ __forceinline__ void fsplit(float x, __half& h, __half& l) {
    h = __float2half_rn(x);
    l = __float2half_rn(x - __half2float(h));
}

__device__ __forceinline__ void mma16816(float* c,
    uint32_t a0, uint32_t a1, uint32_t a2, uint32_t a3, uint32_t b0, uint32_t b1) {
    asm volatile("mma.sync.aligned.m16n8k16.row.col.f32.f16.f16.f32 "
        "{%0,%1,%2,%3}, {%4,%5,%6,%7}, {%8,%9}, {%0,%1,%2,%3};\n"
        : "+f"(c[0]), "+f"(c[1]), "+f"(c[2]), "+f"(c[3])
        : "r"(a0), "r"(a1), "r"(a2), "r"(a3), "r"(b0), "r"(b1));
}

__device__ __forceinline__ void ldsm4(uint32_t& r0, uint32_t& r1, uint32_t& r2,
                                      uint32_t& r3, uint32_t addr) {
    asm volatile("ldmatrix.sync.aligned.m8n8.x4.shared.b16 {%0,%1,%2,%3}, [%4];"
        : "=r"(r0), "=r"(r1), "=r"(r2), "=r"(r3) : "r"(addr));
}

__device__ __forceinline__ uint32_t pack2(__half lo, __half hi) {
    __half2 t = __halves2half2(lo, hi);
    return *(uint32_t*)&t;
}

// ---------------- weight split kernels ----------------
__global__ void k_split(const float* __restrict__ src, __half* __restrict__ dh,
                        __half* __restrict__ dl, int n) {
    int i = blockIdx.x * 256 + threadIdx.x;
    if (i < n) { __half h, l; fsplit(src[i], h, l); dh[i] = h; dl[i] = l; }
}

__global__ void k_split_srw(const float* __restrict__ srw) {
    int idx = blockIdx.x * 256 + threadIdx.x;
    if (idx >= KCONV * CC) return;
    int co = idx & 255;
    int k  = idx >> 8;
    int ci = k & 255;
    int p  = k >> 8;
    float v = srw[(size_t)co * KCONV + ci * 16 + p];
    __half h, l; fsplit(v, h, l);
    g_wsrh[idx] = h; g_wsrl[idx] = l;
}

// ---------------- prefetch loaders (BM=128, BN=64, BK=32; stride 40 halves) ----------------
__device__ __forceinline__ void gload_A(const float* __restrict__ A, int K,
                                        int m0, int k0, float2 rA[8]) {
    int tid = threadIdx.x;
    #pragma unroll
    for (int i = 0; i < 8; i++) {
        int l = tid + i * 256;
        int m = l >> 4, kp = l & 15;
        rA[i] = *(const float2*)(A + (size_t)(m0 + m) * K + k0 + kp * 2);
    }
}

__device__ __forceinline__ void gstore_A(const float2 rA[8], __half* Ash, __half* Asl) {
    int tid = threadIdx.x;
    #pragma unroll
    for (int i = 0; i < 8; i++) {
        int l = tid + i * 256;
        int m = l >> 4, kp = l & 15;
        __half h0, l0, h1, l1;
        fsplit(rA[i].x, h0, l0); fsplit(rA[i].y, h1, l1);
        ((uint32_t*)Ash)[m * 20 + kp] = pack2(h0, h1);
        ((uint32_t*)Asl)[m * 20 + kp] = pack2(l0, l1);
    }
}

__device__ __forceinline__ void gload_B(const __half* __restrict__ Bh,
                                        const __half* __restrict__ Bl,
                                        int N, int k0, int n0,
                                        __half rBh[8], __half rBl[8]) {
    int tid = threadIdx.x;
    #pragma unroll
    for (int i = 0; i < 8; i++) {
        int l = tid + i * 256;
        int kk = l >> 6, n = l & 63;
        size_t g = (size_t)(k0 + kk) * N + n0 + n;
        rBh[i] = Bh[g];
        rBl[i] = Bl[g];
    }
}

__device__ __forceinline__ void gstore_B(const __half rBh[8], const __half rBl[8],
                                         __half* Bsh, __half* Bsl) {
    int tid = threadIdx.x;
    #pragma unroll
    for (int i = 0; i < 8; i++) {
        int l = tid + i * 256;
        int kk = l >> 6, n = l & 63;
        Bsh[n * 40 + kk] = rBh[i];
        Bsl[n * 40 + kk] = rBl[i];
    }
}

// conv A gather loader (x fp32, NCHW-gathered)
__device__ __forceinline__ void conv_load_A(const float* __restrict__ x,
                                            int m0, int k0, float2 rA[8]) {
    int tid = threadIdx.x;
    int p = k0 >> 8, cib = k0 & 255;
    int kh = p >> 2, kw = p & 3;
    #pragma unroll
    for (int i = 0; i < 8; i++) {
        int l = tid + i * 256;
        int m = l >> 4, kp = l & 15;
        int mm = m0 + m;
        int b = mm >> 10, rem = mm & 1023, oh = rem >> 5, ow = rem & 31;
        size_t g = ((size_t)(b * NTOT + (oh * 4 + kh) * 128 + ow * 4 + kw)) * CC + cib + kp * 2;
        rA[i] = *(const float2*)(x + g);
    }
}

// ---------------- ldmatrix mma step (one BK=32) ----------------
__device__ __forceinline__ void mma_step_ldsm(uint32_t ashU, uint32_t aslU,
                                              uint32_t bshU, uint32_t bslU,
                                              float acc[2][4][4], int wm, int wn,
                                              int aOff, int bOff) {
    #pragma unroll
    for (int kc = 0; kc < 2; kc++) {
        int cB = kc * 32;                        // 16 halves
        uint32_t ah[2][4], al[2][4], bh[4][2], bl[4][2];
        #pragma unroll
        for (int mt = 0; mt < 2; mt++) {
            uint32_t base = (wm * 32 + mt * 16) * 80 + cB;
            ldsm4(ah[mt][0], ah[mt][1], ah[mt][2], ah[mt][3], ashU + base + aOff);
            ldsm4(al[mt][0], al[mt][1], al[mt][2], al[mt][3], aslU + base + aOff);
        }
        #pragma unroll
        for (int pp = 0; pp < 2; pp++) {
            uint32_t base = (wn * 32 + pp * 16) * 80 + cB;
            ldsm4(bh[2*pp][0], bh[2*pp][1], bh[2*pp+1][0], bh[2*pp+1][1], bshU + base + bOff);
            ldsm4(bl[2*pp][0], bl[2*pp][1], bl[2*pp+1][0], bl[2*pp+1][1], bslU + base + bOff);
        }
        #pragma unroll
        for (int mt = 0; mt < 2; mt++)
            #pragma unroll
            for (int nt = 0; nt < 4; nt++) {
                mma16816(acc[mt][nt], ah[mt][0], ah[mt][1], ah[mt][2], ah[mt][3], bh[nt][0], bh[nt][1]);
                mma16816(acc[mt][nt], ah[mt][0], ah[mt][1], ah[mt][2], ah[mt][3], bl[nt][0], bl[nt][1]);
                mma16816(acc[mt][nt], al[mt][0], al[mt][1], al[mt][2], al[mt][3], bh[nt][0], bh[nt][1]);
            }
    }
}

#define GEMM_PROLOG \
    __shared__ __align__(16) __half Ash[128*40], Asl[128*40], Bsh[64*40], Bsl[64*40]; \
    int tid = threadIdx.x; \
    int w = tid >> 5, lane = tid & 31; \
    int gid = lane >> 2, tig = lane & 3; \
    int rr = lane & 7, qq = lane >> 3; \
    int wm = w >> 1, wn = w & 1; \
    uint32_t ashU = (uint32_t)__cvta_generic_to_shared(Ash); \
    uint32_t aslU = (uint32_t)__cvta_generic_to_shared(Asl); \
    uint32_t bshU = (uint32_t)__cvta_generic_to_shared(Bsh); \
    uint32_t bslU = (uint32_t)__cvta_generic_to_shared(Bsl); \
    int aOff = (rr + (qq & 1) * 8) * 80 + ((qq >> 1) * 8) * 2; \
    int bOff = (rr + (qq >> 1) * 8) * 80 + ((qq & 1) * 8) * 2; \
    (void)gid; (void)tig; \
    float acc[2][4][4]; \
    _Pragma("unroll") for (int i = 0; i < 2; i++) \
    _Pragma("unroll") for (int j = 0; j < 4; j++) \
    _Pragma("unroll") for (int t = 0; t < 4; t++) acc[i][j][t] = 0.f;

// ---------------- conv-as-GEMM: M=4096, K=4096, N=256 ----------------
__global__ void __launch_bounds__(256) k_conv_mma(const float* __restrict__ x,
                                                  const float* __restrict__ srb) {
    GEMM_PROLOG
    int n0 = blockIdx.x * 64, m0 = blockIdx.y * 128;
    float2 rA[8]; __half rBh[8], rBl[8];
    conv_load_A(x, m0, 0, rA);
    gload_B(g_wsrh, g_wsrl, CC, 0, n0, rBh, rBl);
    for (int k0 = 0; k0 < KCONV; k0 += 32) {
        gstore_A(rA, Ash, Asl);
        gstore_B(rBh, rBl, Bsh, Bsl);
        __syncthreads();
        if (k0 + 32 < KCONV) {
            conv_load_A(x, m0, k0 + 32, rA);
            gload_B(g_wsrh, g_wsrl, CC, k0 + 32, n0, rBh, rBl);
        }
        mma_step_ldsm(ashU, aslU, bshU, bslU, acc, wm, wn, aOff, bOff);
        __syncthreads();
    }
    #pragma unroll
    for (int mt = 0; mt < 2; mt++)
        #pragma unroll
        for (int nt = 0; nt < 4; nt++) {
            int r0 = m0 + wm * 32 + mt * 16 + gid;
            int cb = n0 + wn * 32 + nt * 8 + tig * 2;
            g_xr[(size_t)r0 * CC + cb]       = acc[mt][nt][0] + srb[cb];
            g_xr[(size_t)r0 * CC + cb + 1]   = acc[mt][nt][1] + srb[cb + 1];
            g_xr[(size_t)(r0+8) * CC + cb]   = acc[mt][nt][2] + srb[cb];
            g_xr[(size_t)(r0+8) * CC + cb+1] = acc[mt][nt][3] + srb[cb + 1];
        }
}

// ---------------- LayerNorm ----------------
__global__ void __launch_bounds__(256) k_layernorm(const float* __restrict__ gamma,
                                                   const float* __restrict__ beta) {
    int row  = blockIdx.x * 8 + (threadIdx.x >> 5);
    int lane = threadIdx.x & 31;
    float* xr = g_xr + (size_t)row * CC;
    float v[8], s = 0.f;
    #pragma unroll
    for (int i = 0; i < 8; i++) { v[i] = xr[lane + i * 32]; s += v[i]; }
    #pragma unroll
    for (int o = 16; o; o >>= 1) s += __shfl_xor_sync(0xffffffffu, s, o);
    float mu = s * (1.f / 256.f), s2 = 0.f;
    #pragma unroll
    for (int i = 0; i < 8; i++) { float d = v[i] - mu; s2 += d * d; }
    #pragma unroll
    for (int o = 16; o; o >>= 1) s2 += __shfl_xor_sync(0xffffffffu, s2, o);
    float rstd = rsqrtf(s2 * (1.f / 256.f) + 1e-5f);
    #pragma unroll
    for (int i = 0; i < 8; i++) {
        int c = lane + i * 32;
        xr[c] = (v[i] - mu) * rstd * gamma[c] + beta[c];
    }
}

// ---------------- KV projection ----------------
__global__ void __launch_bounds__(256) k_kv_mma() {
    GEMM_PROLOG
    int n0 = blockIdx.x * 64, m0 = blockIdx.y * 128;
    float2 rA[8]; __half rBh[8], rBl[8];
    gload_A(g_xr, CC, m0, 0, rA);
    gload_B(g_wkvh, g_wkvl, 2 * CC, 0, n0, rBh, rBl);
    for (int k0 = 0; k0 < CC; k0 += 32) {
        gstore_A(rA, Ash, Asl);
        gstore_B(rBh, rBl, Bsh, Bsl);
        __syncthreads();
        if (k0 + 32 < CC) {
            gload_A(g_xr, CC, m0, k0 + 32, rA);
            gload_B(g_wkvh, g_wkvl, 2 * CC, k0 + 32, n0, rBh, rBl);
        }
        mma_step_ldsm(ashU, aslU, bshU, bslU, acc, wm, wn, aOff, bOff);
        __syncthreads();
    }
    #pragma unroll
    for (int mt = 0; mt < 2; mt++)
        #pragma unroll
        for (int nt = 0; nt < 4; nt++)
            #pragma unroll
            for (int e = 0; e < 4; e++) {
                int r = m0 + wm * 32 + mt * 16 + gid + (e >= 2 ? 8 : 0);
                int n = n0 + wn * 32 + nt * 8 + tig * 2 + (e & 1);
                int b = r >> 10, pos = r & 1023;
                int half = n >> 8, hh = (n >> 5) & 7, d = n & 31;
                size_t dst = ((size_t)((b * NHH + hh) * NKV + pos)) * HDD + d;
                __half v = __float2half_rn(acc[mt][nt][e]);
                if (half == 0) g_kh[dst] = v; else g_vh[dst] = v;
            }
}

// ---------------- Q projection ----------------
__global__ void __launch_bounds__(256) k_qproj_mma(const float* __restrict__ q) {
    GEMM_PROLOG
    int n0 = blockIdx.x * 64, m0 = blockIdx.y * 128;
    float2 rA[8]; __half rBh[8], rBl[8];
    gload_A(q, CC, m0, 0, rA);
    gload_B(g_wqh, g_wql, CC, 0, n0, rBh, rBl);
    for (int k0 = 0; k0 < CC; k0 += 32) {
        gstore_A(rA, Ash, Asl);
        gstore_B(rBh, rBl, Bsh, Bsl);
        __syncthreads();
        if (k0 + 32 < CC) {
            gload_A(q, CC, m0, k0 + 32, rA);
            gload_B(g_wqh, g_wql, CC, k0 + 32, n0, rBh, rBl);
        }
        mma_step_ldsm(ashU, aslU, bshU, bslU, acc, wm, wn, aOff, bOff);
        __syncthreads();
    }
    #pragma unroll
    for (int mt = 0; mt < 2; mt++)
        #pragma unroll
        for (int nt = 0; nt < 4; nt++)
            #pragma unroll
            for (int e = 0; e < 4; e++) {
                int r = m0 + wm * 32 + mt * 16 + gid + (e >= 2 ? 8 : 0);
                int n = n0 + wn * 32 + nt * 8 + tig * 2 + (e & 1);
                g_qhh[(size_t)r * CC + n] = __float2half_rn(acc[mt][nt][e]);
            }
}

// ---------------- Output projection ----------------
__global__ void __launch_bounds__(256) k_proj_mma(const float* __restrict__ bp,
                                                  float* __restrict__ out) {
    GEMM_PROLOG
    int n0 = blockIdx.x * 64, m0 = blockIdx.y * 128;
    float2 rA[8]; __half rBh[8], rBl[8];
    gload_A(g_o, CC, m0, 0, rA);
    gload_B(g_pwh, g_pwl, CC, 0, n0, rBh, rBl);
    for (int k0 = 0; k0 < CC; k0 += 32) {
        gstore_A(rA, Ash, Asl);
        gstore_B(rBh, rBl, Bsh, Bsl);
        __syncthreads();
        if (k0 + 32 < CC) {
            gload_A(g_o, CC, m0, k0 + 32, rA);
            gload_B(g_pwh, g_pwl, CC, k0 + 32, n0, rBh, rBl);
        }
        mma_step_ldsm(ashU, aslU, bshU, bslU, acc, wm, wn, aOff, bOff);
        __syncthreads();
    }
    #pragma unroll
    for (int mt = 0; mt < 2; mt++)
        #pragma unroll
        for (int nt = 0; nt < 4; nt++)
            #pragma unroll
            for (int e = 0; e < 4; e++) {
                int r = m0 + wm * 32 + mt * 16 + gid + (e >= 2 ? 8 : 0);
                int n = n0 + wn * 32 + nt * 8 + tig * 2 + (e & 1);
                out[(size_t)r * CC + n] = acc[mt][nt][e] + bp[n];
            }
}

// ---------------- Flash attention (unchanged from R6) ----------------
#define VT_S 130

__global__ void __launch_bounds__(256) k_attn_flash(const int* __restrict__ qlen) {
    __shared__ __half Ks[128 * 40];
    __shared__ __half Vt[32 * VT_S];

    int tid = threadIdx.x;
    int w = tid >> 5, lane = tid & 31;
    int gid = lane >> 2, tig = lane & 3;
    int h = blockIdx.y;
    int q0 = blockIdx.x * 128;

    int l0 = qlen[0], l1 = qlen[1], l2 = qlen[2];
    int b = 0;
    if (q0 >= l0) b = 1;
    if (q0 >= l0 + l1) b = 2;
    if (q0 >= l0 + l1 + l2) b = 3;

    const __half* Kb = g_kh + ((size_t)(b * NHH + h) * NKV) * HDD;
    const __half* Vb = g_vh + ((size_t)(b * NHH + h) * NKV) * HDD;

    uint32_t aQ[2][4];
    {
        const __half* Qp = g_qhh + (size_t)(q0 + w * 16) * CC + h * HDD;
        #pragma unroll
        for (int kc = 0; kc < 2; kc++) {
            int c = kc * 16 + tig * 2;
            aQ[kc][0] = *(const uint32_t*)(Qp + (size_t)gid * CC + c);
            aQ[kc][1] = *(const uint32_t*)(Qp + (size_t)(gid + 8) * CC + c);
            aQ[kc][2] = *(const uint32_t*)(Qp + (size_t)gid * CC + c + 8);
            aQ[kc][3] = *(const uint32_t*)(Qp + (size_t)(gid + 8) * CC + c + 8);
        }
    }

    float o[4][4];
    #pragma unroll
    for (int i = 0; i < 4; i++)
        #pragma unroll
        for (int j = 0; j < 4; j++) o[i][j] = 0.f;
    float mrow[2] = {-1e30f, -1e30f};
    float lsum[2] = {0.f, 0.f};

    for (int kt = 0; kt < 8; kt++) {
        #pragma unroll
        for (int i = 0; i < 8; i++) {
            int idx = tid + i * 256;
            int key = idx >> 4, dp = idx & 15;
            ((uint32_t*)Ks)[key * 20 + dp] =
                *(const uint32_t*)(Kb + (size_t)(kt * 128 + key) * HDD + dp * 2);
        }
        #pragma unroll
        for (int i = 0; i < 8; i++) {
            int idx = tid + i * 256;
            int key = idx >> 4, dp = idx & 15;
            uint32_t u = *(const uint32_t*)(Vb + (size_t)(kt * 128 + key) * HDD + dp * 2);
            __half2 h2 = *(__half2*)&u;
            Vt[(dp * 2) * VT_S + key]     = __low2half(h2);
            Vt[(dp * 2 + 1) * VT_S + key] = __high2half(h2);
        }
        __syncthreads();

        float c[16][4];
        #pragma unroll
        for (int t = 0; t < 16; t++) {
            c[t][0] = c[t][1] = c[t][2] = c[t][3] = 0.f;
            #pragma unroll
            for (int kc = 0; kc < 2; kc++) {
                int cc = kc * 16 + tig * 2;
                uint32_t b0 = *(const uint32_t*)(Ks + (t * 8 + gid) * 40 + cc);
                uint32_t b1 = *(const uint32_t*)(Ks + (t * 8 + gid) * 40 + cc + 8);
                mma16816(c[t], aQ[kc][0], aQ[kc][1], aQ[kc][2], aQ[kc][3], b0, b1);
            }
        }

        float tm0 = -1e30f, tm1 = -1e30f;
        #pragma unroll
        for (int t = 0; t < 16; t++) {
            tm0 = fmaxf(tm0, fmaxf(c[t][0], c[t][1]));
            tm1 = fmaxf(tm1, fmaxf(c[t][2], c[t][3]));
        }
        tm0 = fmaxf(tm0, __shfl_xor_sync(0xffffffffu, tm0, 1));
        tm0 = fmaxf(tm0, __shfl_xor_sync(0xffffffffu, tm0, 2));
        tm1 = fmaxf(tm1, __shfl_xor_sync(0xffffffffu, tm1, 1));
        tm1 = fmaxf(tm1, __shfl_xor_sync(0xffffffffu, tm1, 2));
        float mn0 = fmaxf(mrow[0], tm0);
        float mn1 = fmaxf(mrow[1], tm1);
        float f0 = exp2f((mrow[0] - mn0) * C2E);
        float f1 = exp2f((mrow[1] - mn1) * C2E);
        mrow[0] = mn0; mrow[1] = mn1;
        lsum[0] *= f0; lsum[1] *= f1;
        #pragma unroll
        for (int nt = 0; nt < 4; nt++) {
            o[nt][0] *= f0; o[nt][1] *= f0;
            o[nt][2] *= f1; o[nt][3] *= f1;
        }
        float ps0 = 0.f, ps1 = 0.f;
        uint32_t pf[16][2];
        #pragma unroll
        for (int t = 0; t < 16; t++) {
            float p0 = exp2f((c[t][0] - mn0) * C2E);
            float p1 = exp2f((c[t][1] - mn0) * C2E);
            float p2 = exp2f((c[t][2] - mn1) * C2E);
            float p3 = exp2f((c[t][3] - mn1) * C2E);
            ps0 += p0 + p1;
            ps1 += p2 + p3;
            pf[t][0] = pack2(__float2half_rn(p0), __float2half_rn(p1));
            pf[t][1] = pack2(__float2half_rn(p2), __float2half_rn(p3));
        }
        lsum[0] += ps0;
        lsum[1] += ps1;

        #pragma unroll
        for (int j = 0; j < 8; j++) {
            uint32_t a0 = pf[2 * j][0];
            uint32_t a1 = pf[2 * j][1];
            uint32_t a2 = pf[2 * j + 1][0];
            uint32_t a3 = pf[2 * j + 1][1];
            #pragma unroll
            for (int nt = 0; nt < 4; nt++) {
                int d = nt * 8 + gid;
                uint32_t b0 = *(const uint32_t*)(Vt + d * VT_S + 16 * j + tig * 2);
                uint32_t b1 = *(const uint32_t*)(Vt + d * VT_S + 16 * j + tig * 2 + 8);
                mma16816(o[nt], a0, a1, a2, a3, b0, b1);
            }
        }
        __syncthreads();
    }

    lsum[0] += __shfl_xor_sync(0xffffffffu, lsum[0], 1);
    lsum[0] += __shfl_xor_sync(0xffffffffu, lsum[0], 2);
    lsum[1] += __shfl_xor_sync(0xffffffffu, lsum[1], 1);
    lsum[1] += __shfl_xor_sync(0xffffffffu, lsum[1], 2);

    float i0 = 1.f / lsum[0], i1 = 1.f / lsum[1];
    float* Op = g_o + (size_t)(q0 + w * 16) * CC + h * HDD;
    #pragma unroll
    for (int nt = 0; nt < 4; nt++) {
        int col = nt * 8 + tig * 2;
        float2 v0 = make_float2(o[nt][0] * i0, o[nt][1] * i0);
        float2 v1 = make_float2(o[nt][2] * i1, o[nt][3] * i1);
        *(float2*)(Op + (size_t)gid * CC + col)       = v0;
        *(float2*)(Op + (size_t)(gid + 8) * CC + col) = v1;
    }
}

// ---------------- launch ----------------
extern "C" void kernel_launch(void* const* d_in, const int* in_sizes, int n_in,
                              void* d_out, int out_size) {
    const float* x      = (const float*)d_in[0];
    const float* q      = (const float*)d_in[1];
    const int*   qlen   = (const int*)  d_in[4];
    const float* w_q    = (const float*)d_in[5];
    const float* w_kv   = (const float*)d_in[6];
    const float* sr_w   = (const float*)d_in[7];
    const float* sr_b   = (const float*)d_in[8];
    const float* ln_g   = (const float*)d_in[9];
    const float* ln_b   = (const float*)d_in[10];
    const float* proj_w = (const float*)d_in[11];
    const float* proj_b = (const float*)d_in[12];
    float* out = (float*)d_out;

    __half *wqh, *wql, *wkvh, *wkvl, *pwh, *pwl;
    cudaGetSymbolAddress((void**)&wqh, g_wqh); cudaGetSymbolAddress((void**)&wql, g_wql);
    cudaGetSymbolAddress((void**)&wkvh,g_wkvh);cudaGetSymbolAddress((void**)&wkvl,g_wkvl);
    cudaGetSymbolAddress((void**)&pwh, g_pwh); cudaGetSymbolAddress((void**)&pwl, g_pwl);

    k_split<<<(CC*CC + 255)/256, 256>>>(w_q, wqh, wql, CC*CC);
    k_split<<<(CC*2*CC + 255)/256, 256>>>(w_kv, wkvh, wkvl, CC*2*CC);
    k_split<<<(CC*CC + 255)/256, 256>>>(proj_w, pwh, pwl, CC*CC);
    k_split_srw<<<(KCONV*CC + 255)/256, 256>>>(sr_w);

    k_conv_mma<<<dim3(CC/64, (BB*NKV)/128), 256>>>(x, sr_b);
    k_layernorm<<<(BB*NKV)/8, 256>>>(ln_g, ln_b);
    k_kv_mma<<<dim3((2*CC)/64, (BB*NKV)/128), 256>>>();
    k_qproj_mma<<<dim3(CC/64, TQ/128), 256>>>(q);
    k_attn_flash<<<dim3(TQ/128, NHH), 256>>>(qlen);
    k_proj_mma<<<dim3(CC/64, TQ/128), 256>>>(proj_b, out);
}

// round 9
// speedup vs baseline: 4.4529x; 1.0293x over previous
#include <cuda_runtime.h>
#include <cuda_fp16.h>
#include <math.h>
#include <stdint.h>

#define BB    4
#define NTOT  16384
#define CC    256
#define NHH   8
#define HDD   32
#define NKV   1024
#define KCONV 4096
#define TQ    16384
#define SCALE 0.17677669529663689f
#define C2E   0.25503486963f   // SCALE * log2(e)

// double-buffered GEMM smem layout (bytes)
#define ABYTES 10240            // 128*40 halves
#define BBYTES 5120             // 64*40 halves
#define BUFB   (2*ABYTES + 2*BBYTES)   // 30720
#define GEMM_SMEM (2*BUFB)             // 61440

// ---------------- scratch (device globals) ----------------
__device__ __half g_wqh[CC*CC],   g_wql[CC*CC];
__device__ __half g_wkvh[CC*2*CC],g_wkvl[CC*2*CC];
__device__ __half g_pwh[CC*CC],   g_pwl[CC*CC];
__device__ __half g_wsrh[KCONV*CC], g_wsrl[KCONV*CC];
__device__ float  g_xr [BB*NKV*CC];
__device__ __half g_kh [BB*NHH*NKV*HDD], g_vh[BB*NHH*NKV*HDD];
__device__ __half g_qhh[TQ*CC];
__device__ float  g_o  [TQ*CC];

// ---------------- helpers ----------------
__device__ __forceinline__ void fsplit(float x, __half& h, __half& l) {
    h = __float2half_rn(x);
    l = __float2half_rn(x - __half2float(h));
}

__device__ __forceinline__ void mma16816(float* c,
    uint32_t a0, uint32_t a1, uint32_t a2, uint32_t a3, uint32_t b0, uint32_t b1) {
    asm volatile("mma.sync.aligned.m16n8k16.row.col.f32.f16.f16.f32 "
        "{%0,%1,%2,%3}, {%4,%5,%6,%7}, {%8,%9}, {%0,%1,%2,%3};\n"
        : "+f"(c[0]), "+f"(c[1]), "+f"(c[2]), "+f"(c[3])
        : "r"(a0), "r"(a1), "r"(a2), "r"(a3), "r"(b0), "r"(b1));
}

__device__ __forceinline__ void ldsm4(uint32_t& r0, uint32_t& r1, uint32_t& r2,
                                      uint32_t& r3, uint32_t addr) {
    asm volatile("ldmatrix.sync.aligned.m8n8.x4.shared.b16 {%0,%1,%2,%3}, [%4];"
        : "=r"(r0), "=r"(r1), "=r"(r2), "=r"(r3) : "r"(addr));
}

__device__ __forceinline__ uint32_t pack2(__half lo, __half hi) {
    __half2 t = __halves2half2(lo, hi);
    return *(uint32_t*)&t;
}

// ---------------- weight split kernels ----------------
__global__ void k_split(const float* __restrict__ src, __half* __restrict__ dh,
                        __half* __restrict__ dl, int n) {
    int i = blockIdx.x * 256 + threadIdx.x;
    if (i < n) { __half h, l; fsplit(src[i], h, l); dh[i] = h; dl[i] = l; }
}

__global__ void k_split_srw(const float* __restrict__ srw) {
    int idx = blockIdx.x * 256 + threadIdx.x;
    if (idx >= KCONV * CC) return;
    int co = idx & 255;
    int k  = idx >> 8;
    int ci = k & 255;
    int p  = k >> 8;
    float v = srw[(size_t)co * KCONV + ci * 16 + p];
    __half h, l; fsplit(v, h, l);
    g_wsrh[idx] = h; g_wsrl[idx] = l;
}

// ---------------- prefetch loaders (BM=128, BN=64, BK=32; stride 40 halves) ----------------
__device__ __forceinline__ void gload_A(const float* __restrict__ A, int K,
                                        int m0, int k0, float2 rA[8]) {
    int tid = threadIdx.x;
    #pragma unroll
    for (int i = 0; i < 8; i++) {
        int l = tid + i * 256;
        int m = l >> 4, kp = l & 15;
        rA[i] = *(const float2*)(A + (size_t)(m0 + m) * K + k0 + kp * 2);
    }
}

__device__ __forceinline__ void gstore_A(const float2 rA[8], __half* Ash, __half* Asl) {
    int tid = threadIdx.x;
    #pragma unroll
    for (int i = 0; i < 8; i++) {
        int l = tid + i * 256;
        int m = l >> 4, kp = l & 15;
        __half h0, l0, h1, l1;
        fsplit(rA[i].x, h0, l0); fsplit(rA[i].y, h1, l1);
        ((uint32_t*)Ash)[m * 20 + kp] = pack2(h0, h1);
        ((uint32_t*)Asl)[m * 20 + kp] = pack2(l0, l1);
    }
}

__device__ __forceinline__ void gload_B(const __half* __restrict__ Bh,
                                        const __half* __restrict__ Bl,
                                        int N, int k0, int n0,
                                        __half rBh[8], __half rBl[8]) {
    int tid = threadIdx.x;
    #pragma unroll
    for (int i = 0; i < 8; i++) {
        int l = tid + i * 256;
        int kk = l >> 6, n = l & 63;
        size_t g = (size_t)(k0 + kk) * N + n0 + n;
        rBh[i] = Bh[g];
        rBl[i] = Bl[g];
    }
}

__device__ __forceinline__ void gstore_B(const __half rBh[8], const __half rBl[8],
                                         __half* Bsh, __half* Bsl) {
    int tid = threadIdx.x;
    #pragma unroll
    for (int i = 0; i < 8; i++) {
        int l = tid + i * 256;
        int kk = l >> 6, n = l & 63;
        Bsh[n * 40 + kk] = rBh[i];
        Bsl[n * 40 + kk] = rBl[i];
    }
}

// conv A gather loader (x fp32, NCHW-gathered)
__device__ __forceinline__ void conv_load_A(const float* __restrict__ x,
                                            int m0, int k0, float2 rA[8]) {
    int tid = threadIdx.x;
    int p = k0 >> 8, cib = k0 & 255;
    int kh = p >> 2, kw = p & 3;
    #pragma unroll
    for (int i = 0; i < 8; i++) {
        int l = tid + i * 256;
        int m = l >> 4, kp = l & 15;
        int mm = m0 + m;
        int b = mm >> 10, rem = mm & 1023, oh = rem >> 5, ow = rem & 31;
        size_t g = ((size_t)(b * NTOT + (oh * 4 + kh) * 128 + ow * 4 + kw)) * CC + cib + kp * 2;
        rA[i] = *(const float2*)(x + g);
    }
}

// ---------------- ldmatrix mma step (one BK=32) ----------------
__device__ __forceinline__ void mma_step_ldsm(uint32_t ashU, uint32_t aslU,
                                              uint32_t bshU, uint32_t bslU,
                                              float acc[2][4][4], int wm, int wn,
                                              int aOff, int bOff) {
    #pragma unroll
    for (int kc = 0; kc < 2; kc++) {
        int cB = kc * 32;                        // 16 halves
        uint32_t ah[2][4], al[2][4], bh[4][2], bl[4][2];
        #pragma unroll
        for (int mt = 0; mt < 2; mt++) {
            uint32_t base = (wm * 32 + mt * 16) * 80 + cB;
            ldsm4(ah[mt][0], ah[mt][1], ah[mt][2], ah[mt][3], ashU + base + aOff);
            ldsm4(al[mt][0], al[mt][1], al[mt][2], al[mt][3], aslU + base + aOff);
        }
        #pragma unroll
        for (int pp = 0; pp < 2; pp++) {
            uint32_t base = (wn * 32 + pp * 16) * 80 + cB;
            ldsm4(bh[2*pp][0], bh[2*pp][1], bh[2*pp+1][0], bh[2*pp+1][1], bshU + base + bOff);
            ldsm4(bl[2*pp][0], bl[2*pp][1], bl[2*pp+1][0], bl[2*pp+1][1], bslU + base + bOff);
        }
        #pragma unroll
        for (int mt = 0; mt < 2; mt++)
            #pragma unroll
            for (int nt = 0; nt < 4; nt++) {
                mma16816(acc[mt][nt], ah[mt][0], ah[mt][1], ah[mt][2], ah[mt][3], bh[nt][0], bh[nt][1]);
                mma16816(acc[mt][nt], ah[mt][0], ah[mt][1], ah[mt][2], ah[mt][3], bl[nt][0], bl[nt][1]);
                mma16816(acc[mt][nt], al[mt][0], al[mt][1], al[mt][2], al[mt][3], bh[nt][0], bh[nt][1]);
            }
    }
}

#define ASHP(b) ((__half*)(smraw + (b)*BUFB))
#define ASLP(b) ((__half*)(smraw + (b)*BUFB + ABYTES))
#define BSHP(b) ((__half*)(smraw + (b)*BUFB + 2*ABYTES))
#define BSLP(b) ((__half*)(smraw + (b)*BUFB + 2*ABYTES + BBYTES))

#define GEMM_PROLOG \
    extern __shared__ __align__(16) unsigned char smraw[]; \
    int tid = threadIdx.x; \
    int w = tid >> 5, lane = tid & 31; \
    int gid = lane >> 2, tig = lane & 3; \
    int rr = lane & 7, qq = lane >> 3; \
    int wm = w >> 1, wn = w & 1; \
    uint32_t smemU = (uint32_t)__cvta_generic_to_shared(smraw); \
    int aOff = (rr + (qq & 1) * 8) * 80 + ((qq >> 1) * 8) * 2; \
    int bOff = (rr + (qq >> 1) * 8) * 80 + ((qq & 1) * 8) * 2; \
    (void)gid; (void)tig; \
    float acc[2][4][4]; \
    _Pragma("unroll") for (int i = 0; i < 2; i++) \
    _Pragma("unroll") for (int j = 0; j < 4; j++) \
    _Pragma("unroll") for (int t = 0; t < 4; t++) acc[i][j][t] = 0.f;

#define GEMM_STEP(cur) do { \
    uint32_t bu = smemU + (cur) * BUFB; \
    mma_step_ldsm(bu, bu + ABYTES, bu + 2*ABYTES, bu + 2*ABYTES + BBYTES, \
                  acc, wm, wn, aOff, bOff); \
} while (0)

// ---------------- conv-as-GEMM: M=4096, K=4096, N=256 ----------------
__global__ void __launch_bounds__(256) k_conv_mma(const float* __restrict__ x,
                                                  const float* __restrict__ srb) {
    GEMM_PROLOG
    int n0 = blockIdx.x * 64, m0 = blockIdx.y * 128;
    float2 rA[8]; __half rBh[8], rBl[8];
    conv_load_A(x, m0, 0, rA);
    gload_B(g_wsrh, g_wsrl, CC, 0, n0, rBh, rBl);
    gstore_A(rA, ASHP(0), ASLP(0));
    gstore_B(rBh, rBl, BSHP(0), BSLP(0));
    for (int k0 = 0; k0 < KCONV; k0 += 32) {
        int cur = (k0 >> 5) & 1;
        __syncthreads();
        bool more = (k0 + 32 < KCONV);
        if (more) {
            conv_load_A(x, m0, k0 + 32, rA);
            gload_B(g_wsrh, g_wsrl, CC, k0 + 32, n0, rBh, rBl);
        }
        GEMM_STEP(cur);
        if (more) {
            gstore_A(rA, ASHP(cur ^ 1), ASLP(cur ^ 1));
            gstore_B(rBh, rBl, BSHP(cur ^ 1), BSLP(cur ^ 1));
        }
    }
    #pragma unroll
    for (int mt = 0; mt < 2; mt++)
        #pragma unroll
        for (int nt = 0; nt < 4; nt++) {
            int r0 = m0 + wm * 32 + mt * 16 + gid;
            int cb = n0 + wn * 32 + nt * 8 + tig * 2;
            g_xr[(size_t)r0 * CC + cb]       = acc[mt][nt][0] + srb[cb];
            g_xr[(size_t)r0 * CC + cb + 1]   = acc[mt][nt][1] + srb[cb + 1];
            g_xr[(size_t)(r0+8) * CC + cb]   = acc[mt][nt][2] + srb[cb];
            g_xr[(size_t)(r0+8) * CC + cb+1] = acc[mt][nt][3] + srb[cb + 1];
        }
}

// ---------------- LayerNorm ----------------
__global__ void __launch_bounds__(256) k_layernorm(const float* __restrict__ gamma,
                                                   const float* __restrict__ beta) {
    int row  = blockIdx.x * 8 + (threadIdx.x >> 5);
    int lane = threadIdx.x & 31;
    float* xr = g_xr + (size_t)row * CC;
    float v[8], s = 0.f;
    #pragma unroll
    for (int i = 0; i < 8; i++) { v[i] = xr[lane + i * 32]; s += v[i]; }
    #pragma unroll
    for (int o = 16; o; o >>= 1) s += __shfl_xor_sync(0xffffffffu, s, o);
    float mu = s * (1.f / 256.f), s2 = 0.f;
    #pragma unroll
    for (int i = 0; i < 8; i++) { float d = v[i] - mu; s2 += d * d; }
    #pragma unroll
    for (int o = 16; o; o >>= 1) s2 += __shfl_xor_sync(0xffffffffu, s2, o);
    float rstd = rsqrtf(s2 * (1.f / 256.f) + 1e-5f);
    #pragma unroll
    for (int i = 0; i < 8; i++) {
        int c = lane + i * 32;
        xr[c] = (v[i] - mu) * rstd * gamma[c] + beta[c];
    }
}

// ---------------- KV projection ----------------
__global__ void __launch_bounds__(256) k_kv_mma() {
    GEMM_PROLOG
    int n0 = blockIdx.x * 64, m0 = blockIdx.y * 128;
    float2 rA[8]; __half rBh[8], rBl[8];
    gload_A(g_xr, CC, m0, 0, rA);
    gload_B(g_wkvh, g_wkvl, 2 * CC, 0, n0, rBh, rBl);
    gstore_A(rA, ASHP(0), ASLP(0));
    gstore_B(rBh, rBl, BSHP(0), BSLP(0));
    for (int k0 = 0; k0 < CC; k0 += 32) {
        int cur = (k0 >> 5) & 1;
        __syncthreads();
        bool more = (k0 + 32 < CC);
        if (more) {
            gload_A(g_xr, CC, m0, k0 + 32, rA);
            gload_B(g_wkvh, g_wkvl, 2 * CC, k0 + 32, n0, rBh, rBl);
        }
        GEMM_STEP(cur);
        if (more) {
            gstore_A(rA, ASHP(cur ^ 1), ASLP(cur ^ 1));
            gstore_B(rBh, rBl, BSHP(cur ^ 1), BSLP(cur ^ 1));
        }
    }
    #pragma unroll
    for (int mt = 0; mt < 2; mt++)
        #pragma unroll
        for (int nt = 0; nt < 4; nt++)
            #pragma unroll
            for (int e = 0; e < 4; e++) {
                int r = m0 + wm * 32 + mt * 16 + gid + (e >= 2 ? 8 : 0);
                int n = n0 + wn * 32 + nt * 8 + tig * 2 + (e & 1);
                int b = r >> 10, pos = r & 1023;
                int half = n >> 8, hh = (n >> 5) & 7, d = n & 31;
                size_t dst = ((size_t)((b * NHH + hh) * NKV + pos)) * HDD + d;
                __half v = __float2half_rn(acc[mt][nt][e]);
                if (half == 0) g_kh[dst] = v; else g_vh[dst] = v;
            }
}

// ---------------- Q projection ----------------
__global__ void __launch_bounds__(256) k_qproj_mma(const float* __restrict__ q) {
    GEMM_PROLOG
    int n0 = blockIdx.x * 64, m0 = blockIdx.y * 128;
    float2 rA[8]; __half rBh[8], rBl[8];
    gload_A(q, CC, m0, 0, rA);
    gload_B(g_wqh, g_wql, CC, 0, n0, rBh, rBl);
    gstore_A(rA, ASHP(0), ASLP(0));
    gstore_B(rBh, rBl, BSHP(0), BSLP(0));
    for (int k0 = 0; k0 < CC; k0 += 32) {
        int cur = (k0 >> 5) & 1;
        __syncthreads();
        bool more = (k0 + 32 < CC);
        if (more) {
            gload_A(q, CC, m0, k0 + 32, rA);
            gload_B(g_wqh, g_wql, CC, k0 + 32, n0, rBh, rBl);
        }
        GEMM_STEP(cur);
        if (more) {
            gstore_A(rA, ASHP(cur ^ 1), ASLP(cur ^ 1));
            gstore_B(rBh, rBl, BSHP(cur ^ 1), BSLP(cur ^ 1));
        }
    }
    #pragma unroll
    for (int mt = 0; mt < 2; mt++)
        #pragma unroll
        for (int nt = 0; nt < 4; nt++)
            #pragma unroll
            for (int e = 0; e < 4; e++) {
                int r = m0 + wm * 32 + mt * 16 + gid + (e >= 2 ? 8 : 0);
                int n = n0 + wn * 32 + nt * 8 + tig * 2 + (e & 1);
                g_qhh[(size_t)r * CC + n] = __float2half_rn(acc[mt][nt][e]);
            }
}

// ---------------- Output projection ----------------
__global__ void __launch_bounds__(256) k_proj_mma(const float* __restrict__ bp,
                                                  float* __restrict__ out) {
    GEMM_PROLOG
    int n0 = blockIdx.x * 64, m0 = blockIdx.y * 128;
    float2 rA[8]; __half rBh[8], rBl[8];
    gload_A(g_o, CC, m0, 0, rA);
    gload_B(g_pwh, g_pwl, CC, 0, n0, rBh, rBl);
    gstore_A(rA, ASHP(0), ASLP(0));
    gstore_B(rBh, rBl, BSHP(0), BSLP(0));
    for (int k0 = 0; k0 < CC; k0 += 32) {
        int cur = (k0 >> 5) & 1;
        __syncthreads();
        bool more = (k0 + 32 < CC);
        if (more) {
            gload_A(g_o, CC, m0, k0 + 32, rA);
            gload_B(g_pwh, g_pwl, CC, k0 + 32, n0, rBh, rBl);
        }
        GEMM_STEP(cur);
        if (more) {
            gstore_A(rA, ASHP(cur ^ 1), ASLP(cur ^ 1));
            gstore_B(rBh, rBl, BSHP(cur ^ 1), BSLP(cur ^ 1));
        }
    }
    #pragma unroll
    for (int mt = 0; mt < 2; mt++)
        #pragma unroll
        for (int nt = 0; nt < 4; nt++)
            #pragma unroll
            for (int e = 0; e < 4; e++) {
                int r = m0 + wm * 32 + mt * 16 + gid + (e >= 2 ? 8 : 0);
                int n = n0 + wn * 32 + nt * 8 + tig * 2 + (e & 1);
                out[(size_t)r * CC + n] = acc[mt][nt][e] + bp[n];
            }
}

// ---------------- Flash attention (unchanged, proven) ----------------
#define VT_S 130

__global__ void __launch_bounds__(256) k_attn_flash(const int* __restrict__ qlen) {
    __shared__ __half Ks[128 * 40];
    __shared__ __half Vt[32 * VT_S];

    int tid = threadIdx.x;
    int w = tid >> 5, lane = tid & 31;
    int gid = lane >> 2, tig = lane & 3;
    int h = blockIdx.y;
    int q0 = blockIdx.x * 128;

    int l0 = qlen[0], l1 = qlen[1], l2 = qlen[2];
    int b = 0;
    if (q0 >= l0) b = 1;
    if (q0 >= l0 + l1) b = 2;
    if (q0 >= l0 + l1 + l2) b = 3;

    const __half* Kb = g_kh + ((size_t)(b * NHH + h) * NKV) * HDD;
    const __half* Vb = g_vh + ((size_t)(b * NHH + h) * NKV) * HDD;

    uint32_t aQ[2][4];
    {
        const __half* Qp = g_qhh + (size_t)(q0 + w * 16) * CC + h * HDD;
        #pragma unroll
        for (int kc = 0; kc < 2; kc++) {
            int c = kc * 16 + tig * 2;
            aQ[kc][0] = *(const uint32_t*)(Qp + (size_t)gid * CC + c);
            aQ[kc][1] = *(const uint32_t*)(Qp + (size_t)(gid + 8) * CC + c);
            aQ[kc][2] = *(const uint32_t*)(Qp + (size_t)gid * CC + c + 8);
            aQ[kc][3] = *(const uint32_t*)(Qp + (size_t)(gid + 8) * CC + c + 8);
        }
    }

    float o[4][4];
    #pragma unroll
    for (int i = 0; i < 4; i++)
        #pragma unroll
        for (int j = 0; j < 4; j++) o[i][j] = 0.f;
    float mrow[2] = {-1e30f, -1e30f};
    float lsum[2] = {0.f, 0.f};

    for (int kt = 0; kt < 8; kt++) {
        #pragma unroll
        for (int i = 0; i < 8; i++) {
            int idx = tid + i * 256;
            int key = idx >> 4, dp = idx & 15;
            ((uint32_t*)Ks)[key * 20 + dp] =
                *(const uint32_t*)(Kb + (size_t)(kt * 128 + key) * HDD + dp * 2);
        }
        #pragma unroll
        for (int i = 0; i < 8; i++) {
            int idx = tid + i * 256;
            int key = idx >> 4, dp = idx & 15;
            uint32_t u = *(const uint32_t*)(Vb + (size_t)(kt * 128 + key) * HDD + dp * 2);
            __half2 h2 = *(__half2*)&u;
            Vt[(dp * 2) * VT_S + key]     = __low2half(h2);
            Vt[(dp * 2 + 1) * VT_S + key] = __high2half(h2);
        }
        __syncthreads();

        float c[16][4];
        #pragma unroll
        for (int t = 0; t < 16; t++) {
            c[t][0] = c[t][1] = c[t][2] = c[t][3] = 0.f;
            #pragma unroll
            for (int kc = 0; kc < 2; kc++) {
                int cc = kc * 16 + tig * 2;
                uint32_t b0 = *(const uint32_t*)(Ks + (t * 8 + gid) * 40 + cc);
                uint32_t b1 = *(const uint32_t*)(Ks + (t * 8 + gid) * 40 + cc + 8);
                mma16816(c[t], aQ[kc][0], aQ[kc][1], aQ[kc][2], aQ[kc][3], b0, b1);
            }
        }

        float tm0 = -1e30f, tm1 = -1e30f;
        #pragma unroll
        for (int t = 0; t < 16; t++) {
            tm0 = fmaxf(tm0, fmaxf(c[t][0], c[t][1]));
            tm1 = fmaxf(tm1, fmaxf(c[t][2], c[t][3]));
        }
        tm0 = fmaxf(tm0, __shfl_xor_sync(0xffffffffu, tm0, 1));
        tm0 = fmaxf(tm0, __shfl_xor_sync(0xffffffffu, tm0, 2));
        tm1 = fmaxf(tm1, __shfl_xor_sync(0xffffffffu, tm1, 1));
        tm1 = fmaxf(tm1, __shfl_xor_sync(0xffffffffu, tm1, 2));
        float mn0 = fmaxf(mrow[0], tm0);
        float mn1 = fmaxf(mrow[1], tm1);
        float f0 = exp2f((mrow[0] - mn0) * C2E);
        float f1 = exp2f((mrow[1] - mn1) * C2E);
        mrow[0] = mn0; mrow[1] = mn1;
        lsum[0] *= f0; lsum[1] *= f1;
        #pragma unroll
        for (int nt = 0; nt < 4; nt++) {
            o[nt][0] *= f0; o[nt][1] *= f0;
            o[nt][2] *= f1; o[nt][3] *= f1;
        }
        float ps0 = 0.f, ps1 = 0.f;
        uint32_t pf[16][2];
        #pragma unroll
        for (int t = 0; t < 16; t++) {
            float p0 = exp2f((c[t][0] - mn0) * C2E);
            float p1 = exp2f((c[t][1] - mn0) * C2E);
            float p2 = exp2f((c[t][2] - mn1) * C2E);
            float p3 = exp2f((c[t][3] - mn1) * C2E);
            ps0 += p0 + p1;
            ps1 += p2 + p3;
            pf[t][0] = pack2(__float2half_rn(p0), __float2half_rn(p1));
            pf[t][1] = pack2(__float2half_rn(p2), __float2half_rn(p3));
        }
        lsum[0] += ps0;
        lsum[1] += ps1;

        #pragma unroll
        for (int j = 0; j < 8; j++) {
            uint32_t a0 = pf[2 * j][0];
            uint32_t a1 = pf[2 * j][1];
            uint32_t a2 = pf[2 * j + 1][0];
            uint32_t a3 = pf[2 * j + 1][1];
            #pragma unroll
            for (int nt = 0; nt < 4; nt++) {
                int d = nt * 8 + gid;
                uint32_t b0 = *(const uint32_t*)(Vt + d * VT_S + 16 * j + tig * 2);
                uint32_t b1 = *(const uint32_t*)(Vt + d * VT_S + 16 * j + tig * 2 + 8);
                mma16816(o[nt], a0, a1, a2, a3, b0, b1);
            }
        }
        __syncthreads();
    }

    lsum[0] += __shfl_xor_sync(0xffffffffu, lsum[0], 1);
    lsum[0] += __shfl_xor_sync(0xffffffffu, lsum[0], 2);
    lsum[1] += __shfl_xor_sync(0xffffffffu, lsum[1], 1);
    lsum[1] += __shfl_xor_sync(0xffffffffu, lsum[1], 2);

    float i0 = 1.f / lsum[0], i1 = 1.f / lsum[1];
    float* Op = g_o + (size_t)(q0 + w * 16) * CC + h * HDD;
    #pragma unroll
    for (int nt = 0; nt < 4; nt++) {
        int col = nt * 8 + tig * 2;
        float2 v0 = make_float2(o[nt][0] * i0, o[nt][1] * i0);
        float2 v1 = make_float2(o[nt][2] * i1, o[nt][3] * i1);
        *(float2*)(Op + (size_t)gid * CC + col)       = v0;
        *(float2*)(Op + (size_t)(gid + 8) * CC + col) = v1;
    }
}

// ---------------- launch ----------------
extern "C" void kernel_launch(void* const* d_in, const int* in_sizes, int n_in,
                              void* d_out, int out_size) {
    const float* x      = (const float*)d_in[0];
    const float* q      = (const float*)d_in[1];
    const int*   qlen   = (const int*)  d_in[4];
    const float* w_q    = (const float*)d_in[5];
    const float* w_kv   = (const float*)d_in[6];
    const float* sr_w   = (const float*)d_in[7];
    const float* sr_b   = (const float*)d_in[8];
    const float* ln_g   = (const float*)d_in[9];
    const float* ln_b   = (const float*)d_in[10];
    const float* proj_w = (const float*)d_in[11];
    const float* proj_b = (const float*)d_in[12];
    float* out = (float*)d_out;

    cudaFuncSetAttribute(k_conv_mma,  cudaFuncAttributeMaxDynamicSharedMemorySize, GEMM_SMEM);
    cudaFuncSetAttribute(k_kv_mma,    cudaFuncAttributeMaxDynamicSharedMemorySize, GEMM_SMEM);
    cudaFuncSetAttribute(k_qproj_mma, cudaFuncAttributeMaxDynamicSharedMemorySize, GEMM_SMEM);
    cudaFuncSetAttribute(k_proj_mma,  cudaFuncAttributeMaxDynamicSharedMemorySize, GEMM_SMEM);

    __half *wqh, *wql, *wkvh, *wkvl, *pwh, *pwl;
    cudaGetSymbolAddress((void**)&wqh, g_wqh); cudaGetSymbolAddress((void**)&wql, g_wql);
    cudaGetSymbolAddress((void**)&wkvh,g_wkvh);cudaGetSymbolAddress((void**)&wkvl,g_wkvl);
    cudaGetSymbolAddress((void**)&pwh, g_pwh); cudaGetSymbolAddress((void**)&pwl, g_pwl);

    k_split<<<(CC*CC + 255)/256, 256>>>(w_q, wqh, wql, CC*CC);
    k_split<<<(CC*2*CC + 255)/256, 256>>>(w_kv, wkvh, wkvl, CC*2*CC);
    k_split<<<(CC*CC + 255)/256, 256>>>(proj_w, pwh, pwl, CC*CC);
    k_split_srw<<<(KCONV*CC + 255)/256, 256>>>(sr_w);

    k_conv_mma<<<dim3(CC/64, (BB*NKV)/128), 256, GEMM_SMEM>>>(x, sr_b);
    k_layernorm<<<(BB*NKV)/8, 256>>>(ln_g, ln_b);
    k_kv_mma<<<dim3((2*CC)/64, (BB*NKV)/128), 256, GEMM_SMEM>>>();
    k_qproj_mma<<<dim3(CC/64, TQ/128), 256, GEMM_SMEM>>>(q);
    k_attn_flash<<<dim3(TQ/128, NHH), 256>>>(qlen);
    k_proj_mma<<<dim3(CC/64, TQ/128), 256, GEMM_SMEM>>>(proj_b, out);
}

// round 10
// speedup vs baseline: 4.7266x; 1.0615x over previous
#include <cuda_runtime.h>
#include <cuda_fp16.h>
#include <math.h>
#include <stdint.h>

#define BB    4
#define NTOT  16384
#define CC    256
#define NHH   8
#define HDD   32
#define NKV   1024
#define KCONV 4096
#define TQ    16384
#define SCALE 0.17677669529663689f
#define C2E   0.25503486963f   // SCALE * log2(e)

// double-buffered GEMM smem layout (bytes): A single, B hi/lo
#define ABYTES 10240            // 128*40 halves
#define BBYTES 5120             // 64*40 halves
#define BUFB   (ABYTES + 2*BBYTES)     // 20480
#define GEMM_SMEM (2*BUFB)             // 40960

// ---------------- scratch (device globals) ----------------
__device__ __half g_wqh[CC*CC],   g_wql[CC*CC];
__device__ __half g_wkvh[CC*2*CC],g_wkvl[CC*2*CC];
__device__ __half g_pwh[CC*CC],   g_pwl[CC*CC];
__device__ __half g_wsrh[KCONV*CC], g_wsrl[KCONV*CC];
__device__ float  g_xr [BB*NKV*CC];
__device__ __half g_kh [BB*NHH*NKV*HDD], g_vh[BB*NHH*NKV*HDD];
__device__ __half g_qhh[TQ*CC];
__device__ float  g_o  [TQ*CC];

// ---------------- helpers ----------------
__device__ __forceinline__ void fsplit(float x, __half& h, __half& l) {
    h = __float2half_rn(x);
    l = __float2half_rn(x - __half2float(h));
}

__device__ __forceinline__ void mma16816(float* c,
    uint32_t a0, uint32_t a1, uint32_t a2, uint32_t a3, uint32_t b0, uint32_t b1) {
    asm volatile("mma.sync.aligned.m16n8k16.row.col.f32.f16.f16.f32 "
        "{%0,%1,%2,%3}, {%4,%5,%6,%7}, {%8,%9}, {%0,%1,%2,%3};\n"
        : "+f"(c[0]), "+f"(c[1]), "+f"(c[2]), "+f"(c[3])
        : "r"(a0), "r"(a1), "r"(a2), "r"(a3), "r"(b0), "r"(b1));
}

__device__ __forceinline__ void ldsm4(uint32_t& r0, uint32_t& r1, uint32_t& r2,
                                      uint32_t& r3, uint32_t addr) {
    asm volatile("ldmatrix.sync.aligned.m8n8.x4.shared.b16 {%0,%1,%2,%3}, [%4];"
        : "=r"(r0), "=r"(r1), "=r"(r2), "=r"(r3) : "r"(addr));
}

__device__ __forceinline__ uint32_t pack2(__half lo, __half hi) {
    __half2 t = __halves2half2(lo, hi);
    return *(uint32_t*)&t;
}

// ---------------- weight split kernels ----------------
__global__ void k_split(const float* __restrict__ src, __half* __restrict__ dh,
                        __half* __restrict__ dl, int n) {
    int i = blockIdx.x * 256 + threadIdx.x;
    if (i < n) { __half h, l; fsplit(src[i], h, l); dh[i] = h; dl[i] = l; }
}

__global__ void k_split_srw(const float* __restrict__ srw) {
    int idx = blockIdx.x * 256 + threadIdx.x;
    if (idx >= KCONV * CC) return;
    int co = idx & 255;
    int k  = idx >> 8;
    int ci = k & 255;
    int p  = k >> 8;
    float v = srw[(size_t)co * KCONV + ci * 16 + p];
    __half h, l; fsplit(v, h, l);
    g_wsrh[idx] = h; g_wsrl[idx] = l;
}

// ---------------- prefetch loaders (BM=128, BN=64, BK=32; stride 40 halves) ----------------
__device__ __forceinline__ void gload_A(const float* __restrict__ A, int K,
                                        int m0, int k0, float2 rA[8]) {
    int tid = threadIdx.x;
    #pragma unroll
    for (int i = 0; i < 8; i++) {
        int l = tid + i * 256;
        int m = l >> 4, kp = l & 15;
        rA[i] = *(const float2*)(A + (size_t)(m0 + m) * K + k0 + kp * 2);
    }
}

// A: single fp16 now (no lo array)
__device__ __forceinline__ void gstore_A(const float2 rA[8], __half* Ash) {
    int tid = threadIdx.x;
    #pragma unroll
    for (int i = 0; i < 8; i++) {
        int l = tid + i * 256;
        int m = l >> 4, kp = l & 15;
        ((uint32_t*)Ash)[m * 20 + kp] =
            pack2(__float2half_rn(rA[i].x), __float2half_rn(rA[i].y));
    }
}

__device__ __forceinline__ void gload_B(const __half* __restrict__ Bh,
                                        const __half* __restrict__ Bl,
                                        int N, int k0, int n0,
                                        __half rBh[8], __half rBl[8]) {
    int tid = threadIdx.x;
    #pragma unroll
    for (int i = 0; i < 8; i++) {
        int l = tid + i * 256;
        int kk = l >> 6, n = l & 63;
        size_t g = (size_t)(k0 + kk) * N + n0 + n;
        rBh[i] = Bh[g];
        rBl[i] = Bl[g];
    }
}

__device__ __forceinline__ void gstore_B(const __half rBh[8], const __half rBl[8],
                                         __half* Bsh, __half* Bsl) {
    int tid = threadIdx.x;
    #pragma unroll
    for (int i = 0; i < 8; i++) {
        int l = tid + i * 256;
        int kk = l >> 6, n = l & 63;
        Bsh[n * 40 + kk] = rBh[i];
        Bsl[n * 40 + kk] = rBl[i];
    }
}

// conv A gather loader (x fp32, NCHW-gathered)
__device__ __forceinline__ void conv_load_A(const float* __restrict__ x,
                                            int m0, int k0, float2 rA[8]) {
    int tid = threadIdx.x;
    int p = k0 >> 8, cib = k0 & 255;
    int kh = p >> 2, kw = p & 3;
    #pragma unroll
    for (int i = 0; i < 8; i++) {
        int l = tid + i * 256;
        int m = l >> 4, kp = l & 15;
        int mm = m0 + m;
        int b = mm >> 10, rem = mm & 1023, oh = rem >> 5, ow = rem & 31;
        size_t g = ((size_t)(b * NTOT + (oh * 4 + kh) * 128 + ow * 4 + kw)) * CC + cib + kp * 2;
        rA[i] = *(const float2*)(x + g);
    }
}

// ---------------- ldmatrix mma step (one BK=32): A single, B split, 2 mmas ----------------
__device__ __forceinline__ void mma_step_ldsm(uint32_t ashU,
                                              uint32_t bshU, uint32_t bslU,
                                              float acc[2][4][4], int wm, int wn,
                                              int aOff, int bOff) {
    #pragma unroll
    for (int kc = 0; kc < 2; kc++) {
        int cB = kc * 32;                        // 16 halves
        uint32_t ah[2][4], bh[4][2], bl[4][2];
        #pragma unroll
        for (int mt = 0; mt < 2; mt++) {
            uint32_t base = (wm * 32 + mt * 16) * 80 + cB;
            ldsm4(ah[mt][0], ah[mt][1], ah[mt][2], ah[mt][3], ashU + base + aOff);
        }
        #pragma unroll
        for (int pp = 0; pp < 2; pp++) {
            uint32_t base = (wn * 32 + pp * 16) * 80 + cB;
            ldsm4(bh[2*pp][0], bh[2*pp][1], bh[2*pp+1][0], bh[2*pp+1][1], bshU + base + bOff);
            ldsm4(bl[2*pp][0], bl[2*pp][1], bl[2*pp+1][0], bl[2*pp+1][1], bslU + base + bOff);
        }
        #pragma unroll
        for (int mt = 0; mt < 2; mt++)
            #pragma unroll
            for (int nt = 0; nt < 4; nt++) {
                mma16816(acc[mt][nt], ah[mt][0], ah[mt][1], ah[mt][2], ah[mt][3], bh[nt][0], bh[nt][1]);
                mma16816(acc[mt][nt], ah[mt][0], ah[mt][1], ah[mt][2], ah[mt][3], bl[nt][0], bl[nt][1]);
            }
    }
}

#define ASHP(b) ((__half*)(smraw + (b)*BUFB))
#define BSHP(b) ((__half*)(smraw + (b)*BUFB + ABYTES))
#define BSLP(b) ((__half*)(smraw + (b)*BUFB + ABYTES + BBYTES))

#define GEMM_PROLOG \
    extern __shared__ __align__(16) unsigned char smraw[]; \
    int tid = threadIdx.x; \
    int w = tid >> 5, lane = tid & 31; \
    int gid = lane >> 2, tig = lane & 3; \
    int rr = lane & 7, qq = lane >> 3; \
    int wm = w >> 1, wn = w & 1; \
    uint32_t smemU = (uint32_t)__cvta_generic_to_shared(smraw); \
    int aOff = (rr + (qq & 1) * 8) * 80 + ((qq >> 1) * 8) * 2; \
    int bOff = (rr + (qq >> 1) * 8) * 80 + ((qq & 1) * 8) * 2; \
    (void)gid; (void)tig; \
    float acc[2][4][4]; \
    _Pragma("unroll") for (int i = 0; i < 2; i++) \
    _Pragma("unroll") for (int j = 0; j < 4; j++) \
    _Pragma("unroll") for (int t = 0; t < 4; t++) acc[i][j][t] = 0.f;

#define GEMM_STEP(cur) do { \
    uint32_t bu = smemU + (cur) * BUFB; \
    mma_step_ldsm(bu, bu + ABYTES, bu + ABYTES + BBYTES, \
                  acc, wm, wn, aOff, bOff); \
} while (0)

// ---------------- conv-as-GEMM: M=4096, K=4096, N=256 ----------------
__global__ void __launch_bounds__(256) k_conv_mma(const float* __restrict__ x,
                                                  const float* __restrict__ srb) {
    GEMM_PROLOG
    int n0 = blockIdx.x * 64, m0 = blockIdx.y * 128;
    float2 rA[8]; __half rBh[8], rBl[8];
    conv_load_A(x, m0, 0, rA);
    gload_B(g_wsrh, g_wsrl, CC, 0, n0, rBh, rBl);
    gstore_A(rA, ASHP(0));
    gstore_B(rBh, rBl, BSHP(0), BSLP(0));
    for (int k0 = 0; k0 < KCONV; k0 += 32) {
        int cur = (k0 >> 5) & 1;
        __syncthreads();
        bool more = (k0 + 32 < KCONV);
        if (more) {
            conv_load_A(x, m0, k0 + 32, rA);
            gload_B(g_wsrh, g_wsrl, CC, k0 + 32, n0, rBh, rBl);
        }
        GEMM_STEP(cur);
        if (more) {
            gstore_A(rA, ASHP(cur ^ 1));
            gstore_B(rBh, rBl, BSHP(cur ^ 1), BSLP(cur ^ 1));
        }
    }
    #pragma unroll
    for (int mt = 0; mt < 2; mt++)
        #pragma unroll
        for (int nt = 0; nt < 4; nt++) {
            int r0 = m0 + wm * 32 + mt * 16 + gid;
            int cb = n0 + wn * 32 + nt * 8 + tig * 2;
            g_xr[(size_t)r0 * CC + cb]       = acc[mt][nt][0] + srb[cb];
            g_xr[(size_t)r0 * CC + cb + 1]   = acc[mt][nt][1] + srb[cb + 1];
            g_xr[(size_t)(r0+8) * CC + cb]   = acc[mt][nt][2] + srb[cb];
            g_xr[(size_t)(r0+8) * CC + cb+1] = acc[mt][nt][3] + srb[cb + 1];
        }
}

// ---------------- LayerNorm ----------------
__global__ void __launch_bounds__(256) k_layernorm(const float* __restrict__ gamma,
                                                   const float* __restrict__ beta) {
    int row  = blockIdx.x * 8 + (threadIdx.x >> 5);
    int lane = threadIdx.x & 31;
    float* xr = g_xr + (size_t)row * CC;
    float v[8], s = 0.f;
    #pragma unroll
    for (int i = 0; i < 8; i++) { v[i] = xr[lane + i * 32]; s += v[i]; }
    #pragma unroll
    for (int o = 16; o; o >>= 1) s += __shfl_xor_sync(0xffffffffu, s, o);
    float mu = s * (1.f / 256.f), s2 = 0.f;
    #pragma unroll
    for (int i = 0; i < 8; i++) { float d = v[i] - mu; s2 += d * d; }
    #pragma unroll
    for (int o = 16; o; o >>= 1) s2 += __shfl_xor_sync(0xffffffffu, s2, o);
    float rstd = rsqrtf(s2 * (1.f / 256.f) + 1e-5f);
    #pragma unroll
    for (int i = 0; i < 8; i++) {
        int c = lane + i * 32;
        xr[c] = (v[i] - mu) * rstd * gamma[c] + beta[c];
    }
}

// ---------------- KV projection ----------------
__global__ void __launch_bounds__(256) k_kv_mma() {
    GEMM_PROLOG
    int n0 = blockIdx.x * 64, m0 = blockIdx.y * 128;
    float2 rA[8]; __half rBh[8], rBl[8];
    gload_A(g_xr, CC, m0, 0, rA);
    gload_B(g_wkvh, g_wkvl, 2 * CC, 0, n0, rBh, rBl);
    gstore_A(rA, ASHP(0));
    gstore_B(rBh, rBl, BSHP(0), BSLP(0));
    for (int k0 = 0; k0 < CC; k0 += 32) {
        int cur = (k0 >> 5) & 1;
        __syncthreads();
        bool more = (k0 + 32 < CC);
        if (more) {
            gload_A(g_xr, CC, m0, k0 + 32, rA);
            gload_B(g_wkvh, g_wkvl, 2 * CC, k0 + 32, n0, rBh, rBl);
        }
        GEMM_STEP(cur);
        if (more) {
            gstore_A(rA, ASHP(cur ^ 1));
            gstore_B(rBh, rBl, BSHP(cur ^ 1), BSLP(cur ^ 1));
        }
    }
    #pragma unroll
    for (int mt = 0; mt < 2; mt++)
        #pragma unroll
        for (int nt = 0; nt < 4; nt++)
            #pragma unroll
            for (int e = 0; e < 4; e++) {
                int r = m0 + wm * 32 + mt * 16 + gid + (e >= 2 ? 8 : 0);
                int n = n0 + wn * 32 + nt * 8 + tig * 2 + (e & 1);
                int b = r >> 10, pos = r & 1023;
                int half = n >> 8, hh = (n >> 5) & 7, d = n & 31;
                size_t dst = ((size_t)((b * NHH + hh) * NKV + pos)) * HDD + d;
                __half v = __float2half_rn(acc[mt][nt][e]);
                if (half == 0) g_kh[dst] = v; else g_vh[dst] = v;
            }
}

// ---------------- Q projection ----------------
__global__ void __launch_bounds__(256) k_qproj_mma(const float* __restrict__ q) {
    GEMM_PROLOG
    int n0 = blockIdx.x * 64, m0 = blockIdx.y * 128;
    float2 rA[8]; __half rBh[8], rBl[8];
    gload_A(q, CC, m0, 0, rA);
    gload_B(g_wqh, g_wql, CC, 0, n0, rBh, rBl);
    gstore_A(rA, ASHP(0));
    gstore_B(rBh, rBl, BSHP(0), BSLP(0));
    for (int k0 = 0; k0 < CC; k0 += 32) {
        int cur = (k0 >> 5) & 1;
        __syncthreads();
        bool more = (k0 + 32 < CC);
        if (more) {
            gload_A(q, CC, m0, k0 + 32, rA);
            gload_B(g_wqh, g_wql, CC, k0 + 32, n0, rBh, rBl);
        }
        GEMM_STEP(cur);
        if (more) {
            gstore_A(rA, ASHP(cur ^ 1));
            gstore_B(rBh, rBl, BSHP(cur ^ 1), BSLP(cur ^ 1));
        }
    }
    #pragma unroll
    for (int mt = 0; mt < 2; mt++)
        #pragma unroll
        for (int nt = 0; nt < 4; nt++)
            #pragma unroll
            for (int e = 0; e < 4; e++) {
                int r = m0 + wm * 32 + mt * 16 + gid + (e >= 2 ? 8 : 0);
                int n = n0 + wn * 32 + nt * 8 + tig * 2 + (e & 1);
                g_qhh[(size_t)r * CC + n] = __float2half_rn(acc[mt][nt][e]);
            }
}

// ---------------- Output projection ----------------
__global__ void __launch_bounds__(256) k_proj_mma(const float* __restrict__ bp,
                                                  float* __restrict__ out) {
    GEMM_PROLOG
    int n0 = blockIdx.x * 64, m0 = blockIdx.y * 128;
    float2 rA[8]; __half rBh[8], rBl[8];
    gload_A(g_o, CC, m0, 0, rA);
    gload_B(g_pwh, g_pwl, CC, 0, n0, rBh, rBl);
    gstore_A(rA, ASHP(0));
    gstore_B(rBh, rBl, BSHP(0), BSLP(0));
    for (int k0 = 0; k0 < CC; k0 += 32) {
        int cur = (k0 >> 5) & 1;
        __syncthreads();
        bool more = (k0 + 32 < CC);
        if (more) {
            gload_A(g_o, CC, m0, k0 + 32, rA);
            gload_B(g_pwh, g_pwl, CC, k0 + 32, n0, rBh, rBl);
        }
        GEMM_STEP(cur);
        if (more) {
            gstore_A(rA, ASHP(cur ^ 1));
            gstore_B(rBh, rBl, BSHP(cur ^ 1), BSLP(cur ^ 1));
        }
    }
    #pragma unroll
    for (int mt = 0; mt < 2; mt++)
        #pragma unroll
        for (int nt = 0; nt < 4; nt++)
            #pragma unroll
            for (int e = 0; e < 4; e++) {
                int r = m0 + wm * 32 + mt * 16 + gid + (e >= 2 ? 8 : 0);
                int n = n0 + wn * 32 + nt * 8 + tig * 2 + (e & 1);
                out[(size_t)r * CC + n] = acc[mt][nt][e] + bp[n];
            }
}

// ---------------- Flash attention (unchanged, proven) ----------------
#define VT_S 130

__global__ void __launch_bounds__(256) k_attn_flash(const int* __restrict__ qlen) {
    __shared__ __half Ks[128 * 40];
    __shared__ __half Vt[32 * VT_S];

    int tid = threadIdx.x;
    int w = tid >> 5, lane = tid & 31;
    int gid = lane >> 2, tig = lane & 3;
    int h = blockIdx.y;
    int q0 = blockIdx.x * 128;

    int l0 = qlen[0], l1 = qlen[1], l2 = qlen[2];
    int b = 0;
    if (q0 >= l0) b = 1;
    if (q0 >= l0 + l1) b = 2;
    if (q0 >= l0 + l1 + l2) b = 3;

    const __half* Kb = g_kh + ((size_t)(b * NHH + h) * NKV) * HDD;
    const __half* Vb = g_vh + ((size_t)(b * NHH + h) * NKV) * HDD;

    uint32_t aQ[2][4];
    {
        const __half* Qp = g_qhh + (size_t)(q0 + w * 16) * CC + h * HDD;
        #pragma unroll
        for (int kc = 0; kc < 2; kc++) {
            int c = kc * 16 + tig * 2;
            aQ[kc][0] = *(const uint32_t*)(Qp + (size_t)gid * CC + c);
            aQ[kc][1] = *(const uint32_t*)(Qp + (size_t)(gid + 8) * CC + c);
            aQ[kc][2] = *(const uint32_t*)(Qp + (size_t)gid * CC + c + 8);
            aQ[kc][3] = *(const uint32_t*)(Qp + (size_t)(gid + 8) * CC + c + 8);
        }
    }

    float o[4][4];
    #pragma unroll
    for (int i = 0; i < 4; i++)
        #pragma unroll
        for (int j = 0; j < 4; j++) o[i][j] = 0.f;
    float mrow[2] = {-1e30f, -1e30f};
    float lsum[2] = {0.f, 0.f};

    for (int kt = 0; kt < 8; kt++) {
        #pragma unroll
        for (int i = 0; i < 8; i++) {
            int idx = tid + i * 256;
            int key = idx >> 4, dp = idx & 15;
            ((uint32_t*)Ks)[key * 20 + dp] =
                *(const uint32_t*)(Kb + (size_t)(kt * 128 + key) * HDD + dp * 2);
        }
        #pragma unroll
        for (int i = 0; i < 8; i++) {
            int idx = tid + i * 256;
            int key = idx >> 4, dp = idx & 15;
            uint32_t u = *(const uint32_t*)(Vb + (size_t)(kt * 128 + key) * HDD + dp * 2);
            __half2 h2 = *(__half2*)&u;
            Vt[(dp * 2) * VT_S + key]     = __low2half(h2);
            Vt[(dp * 2 + 1) * VT_S + key] = __high2half(h2);
        }
        __syncthreads();

        float c[16][4];
        #pragma unroll
        for (int t = 0; t < 16; t++) {
            c[t][0] = c[t][1] = c[t][2] = c[t][3] = 0.f;
            #pragma unroll
            for (int kc = 0; kc < 2; kc++) {
                int cc = kc * 16 + tig * 2;
                uint32_t b0 = *(const uint32_t*)(Ks + (t * 8 + gid) * 40 + cc);
                uint32_t b1 = *(const uint32_t*)(Ks + (t * 8 + gid) * 40 + cc + 8);
                mma16816(c[t], aQ[kc][0], aQ[kc][1], aQ[kc][2], aQ[kc][3], b0, b1);
            }
        }

        float tm0 = -1e30f, tm1 = -1e30f;
        #pragma unroll
        for (int t = 0; t < 16; t++) {
            tm0 = fmaxf(tm0, fmaxf(c[t][0], c[t][1]));
            tm1 = fmaxf(tm1, fmaxf(c[t][2], c[t][3]));
        }
        tm0 = fmaxf(tm0, __shfl_xor_sync(0xffffffffu, tm0, 1));
        tm0 = fmaxf(tm0, __shfl_xor_sync(0xffffffffu, tm0, 2));
        tm1 = fmaxf(tm1, __shfl_xor_sync(0xffffffffu, tm1, 1));
        tm1 = fmaxf(tm1, __shfl_xor_sync(0xffffffffu, tm1, 2));
        float mn0 = fmaxf(mrow[0], tm0);
        float mn1 = fmaxf(mrow[1], tm1);
        float f0 = exp2f((mrow[0] - mn0) * C2E);
        float f1 = exp2f((mrow[1] - mn1) * C2E);
        mrow[0] = mn0; mrow[1] = mn1;
        lsum[0] *= f0; lsum[1] *= f1;
        #pragma unroll
        for (int nt = 0; nt < 4; nt++) {
            o[nt][0] *= f0; o[nt][1] *= f0;
            o[nt][2] *= f1; o[nt][3] *= f1;
        }
        float ps0 = 0.f, ps1 = 0.f;
        uint32_t pf[16][2];
        #pragma unroll
        for (int t = 0; t < 16; t++) {
            float p0 = exp2f((c[t][0] - mn0) * C2E);
            float p1 = exp2f((c[t][1] - mn0) * C2E);
            float p2 = exp2f((c[t][2] - mn1) * C2E);
            float p3 = exp2f((c[t][3] - mn1) * C2E);
            ps0 += p0 + p1;
            ps1 += p2 + p3;
            pf[t][0] = pack2(__float2half_rn(p0), __float2half_rn(p1));
            pf[t][1] = pack2(__float2half_rn(p2), __float2half_rn(p3));
        }
        lsum[0] += ps0;
        lsum[1] += ps1;

        #pragma unroll
        for (int j = 0; j < 8; j++) {
            uint32_t a0 = pf[2 * j][0];
            uint32_t a1 = pf[2 * j][1];
            uint32_t a2 = pf[2 * j + 1][0];
            uint32_t a3 = pf[2 * j + 1][1];
            #pragma unroll
            for (int nt = 0; nt < 4; nt++) {
                int d = nt * 8 + gid;
                uint32_t b0 = *(const uint32_t*)(Vt + d * VT_S + 16 * j + tig * 2);
                uint32_t b1 = *(const uint32_t*)(Vt + d * VT_S + 16 * j + tig * 2 + 8);
                mma16816(o[nt], a0, a1, a2, a3, b0, b1);
            }
        }
        __syncthreads();
    }

    lsum[0] += __shfl_xor_sync(0xffffffffu, lsum[0], 1);
    lsum[0] += __shfl_xor_sync(0xffffffffu, lsum[0], 2);
    lsum[1] += __shfl_xor_sync(0xffffffffu, lsum[1], 1);
    lsum[1] += __shfl_xor_sync(0xffffffffu, lsum[1], 2);

    float i0 = 1.f / lsum[0], i1 = 1.f / lsum[1];
    float* Op = g_o + (size_t)(q0 + w * 16) * CC + h * HDD;
    #pragma unroll
    for (int nt = 0; nt < 4; nt++) {
        int col = nt * 8 + tig * 2;
        float2 v0 = make_float2(o[nt][0] * i0, o[nt][1] * i0);
        float2 v1 = make_float2(o[nt][2] * i1, o[nt][3] * i1);
        *(float2*)(Op + (size_t)gid * CC + col)       = v0;
        *(float2*)(Op + (size_t)(gid + 8) * CC + col) = v1;
    }
}

// ---------------- launch ----------------
extern "C" void kernel_launch(void* const* d_in, const int* in_sizes, int n_in,
                              void* d_out, int out_size) {
    const float* x      = (const float*)d_in[0];
    const float* q      = (const float*)d_in[1];
    const int*   qlen   = (const int*)  d_in[4];
    const float* w_q    = (const float*)d_in[5];
    const float* w_kv   = (const float*)d_in[6];
    const float* sr_w   = (const float*)d_in[7];
    const float* sr_b   = (const float*)d_in[8];
    const float* ln_g   = (const float*)d_in[9];
    const float* ln_b   = (const float*)d_in[10];
    const float* proj_w = (const float*)d_in[11];
    const float* proj_b = (const float*)d_in[12];
    float* out = (float*)d_out;

    cudaFuncSetAttribute(k_conv_mma,  cudaFuncAttributeMaxDynamicSharedMemorySize, GEMM_SMEM);
    cudaFuncSetAttribute(k_kv_mma,    cudaFuncAttributeMaxDynamicSharedMemorySize, GEMM_SMEM);
    cudaFuncSetAttribute(k_qproj_mma, cudaFuncAttributeMaxDynamicSharedMemorySize, GEMM_SMEM);
    cudaFuncSetAttribute(k_proj_mma,  cudaFuncAttributeMaxDynamicSharedMemorySize, GEMM_SMEM);

    __half *wqh, *wql, *wkvh, *wkvl, *pwh, *pwl;
    cudaGetSymbolAddress((void**)&wqh, g_wqh); cudaGetSymbolAddress((void**)&wql, g_wql);
    cudaGetSymbolAddress((void**)&wkvh,g_wkvh);cudaGetSymbolAddress((void**)&wkvl,g_wkvl);
    cudaGetSymbolAddress((void**)&pwh, g_pwh); cudaGetSymbolAddress((void**)&pwl, g_pwl);

    k_split<<<(CC*CC + 255)/256, 256>>>(w_q, wqh, wql, CC*CC);
    k_split<<<(CC*2*CC + 255)/256, 256>>>(w_kv, wkvh, wkvl, CC*2*CC);
    k_split<<<(CC*CC + 255)/256, 256>>>(proj_w, pwh, pwl, CC*CC);
    k_split_srw<<<(KCONV*CC + 255)/256, 256>>>(sr_w);

    k_conv_mma<<<dim3(CC/64, (BB*NKV)/128), 256, GEMM_SMEM>>>(x, sr_b);
    k_layernorm<<<(BB*NKV)/8, 256>>>(ln_g, ln_b);
    k_kv_mma<<<dim3((2*CC)/64, (BB*NKV)/128), 256, GEMM_SMEM>>>();
    k_qproj_mma<<<dim3(CC/64, TQ/128), 256, GEMM_SMEM>>>(q);
    k_attn_flash<<<dim3(TQ/128, NHH), 256>>>(qlen);
    k_proj_mma<<<dim3(CC/64, TQ/128), 256, GEMM_SMEM>>>(proj_b, out);
}

// round 11
// speedup vs baseline: 5.0963x; 1.0782x over previous
#include <cuda_runtime.h>
#include <cuda_fp16.h>
#include <math.h>
#include <stdint.h>

#define BB    4
#define NTOT  16384
#define CC    256
#define NHH   8
#define HDD   32
#define NKV   1024
#define KCONV 4096
#define TQ    16384
#define SCALE 0.17677669529663689f
#define C2E   0.25503486963f   // SCALE * log2(e)

// GEMM tiles: BM=64, BN=64, BK=32; smem row stride 40 halves (80 B)
#define ABYTES 5120             // 64*40 halves
#define BBYTES 5120             // 64*40 halves
#define BUF1   (ABYTES + BBYTES)        // 10240  (single-B kernels)
#define SMEM1  (2*BUF1)                 // 20480
#define BUF2   (ABYTES + 2*BBYTES)      // 15360  (split-B outproj)
#define SMEM2  (2*BUF2)                 // 30720

// ---------------- scratch (device globals) ----------------
__device__ __half g_wqh [CC*CC];
__device__ __half g_wkvh[CC*2*CC];
__device__ __half g_pwh [CC*CC],  g_pwl[CC*CC];
__device__ __half g_wsrh[KCONV*CC];
__device__ float  g_xr [BB*NKV*CC];
__device__ __half g_kh [BB*NHH*NKV*HDD], g_vh[BB*NHH*NKV*HDD];
__device__ __half g_qhh[TQ*CC];
__device__ float  g_o  [TQ*CC];

// ---------------- helpers ----------------
__device__ __forceinline__ void fsplit(float x, __half& h, __half& l) {
    h = __float2half_rn(x);
    l = __float2half_rn(x - __half2float(h));
}

__device__ __forceinline__ void mma16816(float* c,
    uint32_t a0, uint32_t a1, uint32_t a2, uint32_t a3, uint32_t b0, uint32_t b1) {
    asm volatile("mma.sync.aligned.m16n8k16.row.col.f32.f16.f16.f32 "
        "{%0,%1,%2,%3}, {%4,%5,%6,%7}, {%8,%9}, {%0,%1,%2,%3};\n"
        : "+f"(c[0]), "+f"(c[1]), "+f"(c[2]), "+f"(c[3])
        : "r"(a0), "r"(a1), "r"(a2), "r"(a3), "r"(b0), "r"(b1));
}

__device__ __forceinline__ void ldsm4(uint32_t& r0, uint32_t& r1, uint32_t& r2,
                                      uint32_t& r3, uint32_t addr) {
    asm volatile("ldmatrix.sync.aligned.m8n8.x4.shared.b16 {%0,%1,%2,%3}, [%4];"
        : "=r"(r0), "=r"(r1), "=r"(r2), "=r"(r3) : "r"(addr));
}

__device__ __forceinline__ uint32_t pack2(__half lo, __half hi) {
    __half2 t = __halves2half2(lo, hi);
    return *(uint32_t*)&t;
}

// ---------------- weight convert kernels ----------------
__global__ void k_cvt(const float* __restrict__ src, __half* __restrict__ dh, int n) {
    int i = blockIdx.x * 256 + threadIdx.x;
    if (i < n) dh[i] = __float2half_rn(src[i]);
}

__global__ void k_split(const float* __restrict__ src, __half* __restrict__ dh,
                        __half* __restrict__ dl, int n) {
    int i = blockIdx.x * 256 + threadIdx.x;
    if (i < n) { __half h, l; fsplit(src[i], h, l); dh[i] = h; dl[i] = l; }
}

__global__ void k_cvt_srw(const float* __restrict__ srw) {
    int idx = blockIdx.x * 256 + threadIdx.x;
    if (idx >= KCONV * CC) return;
    int co = idx & 255;
    int k  = idx >> 8;
    int ci = k & 255;
    int p  = k >> 8;
    g_wsrh[idx] = __float2half_rn(srw[(size_t)co * KCONV + ci * 16 + p]);
}

// ---------------- loaders (BM=64, BN=64, BK=32; stride 40 halves) ----------------
__device__ __forceinline__ void gload_A(const float* __restrict__ A, int K,
                                        int m0, int k0, float2 rA[4]) {
    int tid = threadIdx.x;
    #pragma unroll
    for (int i = 0; i < 4; i++) {
        int l = tid + i * 256;
        int m = l >> 4, kp = l & 15;
        rA[i] = *(const float2*)(A + (size_t)(m0 + m) * K + k0 + kp * 2);
    }
}

__device__ __forceinline__ void gstore_A(const float2 rA[4], __half* Ash) {
    int tid = threadIdx.x;
    #pragma unroll
    for (int i = 0; i < 4; i++) {
        int l = tid + i * 256;
        int m = l >> 4, kp = l & 15;
        ((uint32_t*)Ash)[m * 20 + kp] =
            pack2(__float2half_rn(rA[i].x), __float2half_rn(rA[i].y));
    }
}

__device__ __forceinline__ void gload_B1(const __half* __restrict__ Bh,
                                         int N, int k0, int n0, __half rBh[8]) {
    int tid = threadIdx.x;
    #pragma unroll
    for (int i = 0; i < 8; i++) {
        int l = tid + i * 256;
        int kk = l >> 6, n = l & 63;
        rBh[i] = Bh[(size_t)(k0 + kk) * N + n0 + n];
    }
}

__device__ __forceinline__ void gstore_B1(const __half rBh[8], __half* Bsh) {
    int tid = threadIdx.x;
    #pragma unroll
    for (int i = 0; i < 8; i++) {
        int l = tid + i * 256;
        int kk = l >> 6, n = l & 63;
        Bsh[n * 40 + kk] = rBh[i];
    }
}

__device__ __forceinline__ void gload_B2(const __half* __restrict__ Bh,
                                         const __half* __restrict__ Bl,
                                         int N, int k0, int n0,
                                         __half rBh[8], __half rBl[8]) {
    int tid = threadIdx.x;
    #pragma unroll
    for (int i = 0; i < 8; i++) {
        int l = tid + i * 256;
        int kk = l >> 6, n = l & 63;
        size_t g = (size_t)(k0 + kk) * N + n0 + n;
        rBh[i] = Bh[g];
        rBl[i] = Bl[g];
    }
}

__device__ __forceinline__ void gstore_B2(const __half rBh[8], const __half rBl[8],
                                          __half* Bsh, __half* Bsl) {
    int tid = threadIdx.x;
    #pragma unroll
    for (int i = 0; i < 8; i++) {
        int l = tid + i * 256;
        int kk = l >> 6, n = l & 63;
        Bsh[n * 40 + kk] = rBh[i];
        Bsl[n * 40 + kk] = rBl[i];
    }
}

// conv A gather loader (x fp32, NCHW-gathered); BM=64
__device__ __forceinline__ void conv_load_A(const float* __restrict__ x,
                                            int m0, int k0, float2 rA[4]) {
    int tid = threadIdx.x;
    int p = k0 >> 8, cib = k0 & 255;
    int kh = p >> 2, kw = p & 3;
    #pragma unroll
    for (int i = 0; i < 4; i++) {
        int l = tid + i * 256;
        int m = l >> 4, kp = l & 15;
        int mm = m0 + m;
        int b = mm >> 10, rem = mm & 1023, oh = rem >> 5, ow = rem & 31;
        size_t g = ((size_t)(b * NTOT + (oh * 4 + kh) * 128 + ow * 4 + kw)) * CC + cib + kp * 2;
        rA[i] = *(const float2*)(x + g);
    }
}

// ---------------- mma steps (one BK=32), warp tile 16x32 ----------------
__device__ __forceinline__ void mma_step1(uint32_t aU, uint32_t bU,
                                          float acc[4][4], int wm, int wn,
                                          int aOff, int bOff) {
    #pragma unroll
    for (int kc = 0; kc < 2; kc++) {
        int cB = kc * 32;
        uint32_t a[4], bh[4][2];
        ldsm4(a[0], a[1], a[2], a[3], aU + (wm * 16) * 80 + cB + aOff);
        #pragma unroll
        for (int pp = 0; pp < 2; pp++) {
            uint32_t base = (wn * 32 + pp * 16) * 80 + cB;
            ldsm4(bh[2*pp][0], bh[2*pp][1], bh[2*pp+1][0], bh[2*pp+1][1], bU + base + bOff);
        }
        #pragma unroll
        for (int nt = 0; nt < 4; nt++)
            mma16816(acc[nt], a[0], a[1], a[2], a[3], bh[nt][0], bh[nt][1]);
    }
}

__device__ __forceinline__ void mma_step2(uint32_t aU, uint32_t bhU, uint32_t blU,
                                          float acc[4][4], int wm, int wn,
                                          int aOff, int bOff) {
    #pragma unroll
    for (int kc = 0; kc < 2; kc++) {
        int cB = kc * 32;
        uint32_t a[4], bh[4][2], bl[4][2];
        ldsm4(a[0], a[1], a[2], a[3], aU + (wm * 16) * 80 + cB + aOff);
        #pragma unroll
        for (int pp = 0; pp < 2; pp++) {
            uint32_t base = (wn * 32 + pp * 16) * 80 + cB;
            ldsm4(bh[2*pp][0], bh[2*pp][1], bh[2*pp+1][0], bh[2*pp+1][1], bhU + base + bOff);
            ldsm4(bl[2*pp][0], bl[2*pp][1], bl[2*pp+1][0], bl[2*pp+1][1], blU + base + bOff);
        }
        #pragma unroll
        for (int nt = 0; nt < 4; nt++) {
            mma16816(acc[nt], a[0], a[1], a[2], a[3], bh[nt][0], bh[nt][1]);
            mma16816(acc[nt], a[0], a[1], a[2], a[3], bl[nt][0], bl[nt][1]);
        }
    }
}

#define GEMM_PROLOG \
    extern __shared__ __align__(16) unsigned char smraw[]; \
    int tid = threadIdx.x; \
    int w = tid >> 5, lane = tid & 31; \
    int gid = lane >> 2, tig = lane & 3; \
    int rr = lane & 7, qq = lane >> 3; \
    int wm = w & 3, wn = w >> 2; \
    uint32_t smemU = (uint32_t)__cvta_generic_to_shared(smraw); \
    int aOff = (rr + (qq & 1) * 8) * 80 + ((qq >> 1) * 8) * 2; \
    int bOff = (rr + (qq >> 1) * 8) * 80 + ((qq & 1) * 8) * 2; \
    (void)gid; (void)tig; \
    float acc[4][4]; \
    _Pragma("unroll") for (int j = 0; j < 4; j++) \
    _Pragma("unroll") for (int t = 0; t < 4; t++) acc[j][t] = 0.f;

// ---------------- conv-as-GEMM: M=4096, K=4096, N=256 (single-B) ----------------
__global__ void __launch_bounds__(256) k_conv_mma(const float* __restrict__ x,
                                                  const float* __restrict__ srb) {
    GEMM_PROLOG
    int n0 = blockIdx.x * 64, m0 = blockIdx.y * 64;
    float2 rA[4]; __half rBh[8];
    conv_load_A(x, m0, 0, rA);
    gload_B1(g_wsrh, CC, 0, n0, rBh);
    gstore_A(rA, (__half*)smraw);
    gstore_B1(rBh, (__half*)(smraw + ABYTES));
    for (int k0 = 0; k0 < KCONV; k0 += 32) {
        int cur = (k0 >> 5) & 1;
        __syncthreads();
        bool more = (k0 + 32 < KCONV);
        if (more) {
            conv_load_A(x, m0, k0 + 32, rA);
            gload_B1(g_wsrh, CC, k0 + 32, n0, rBh);
        }
        uint32_t bu = smemU + cur * BUF1;
        mma_step1(bu, bu + ABYTES, acc, wm, wn, aOff, bOff);
        if (more) {
            gstore_A(rA, (__half*)(smraw + (cur ^ 1) * BUF1));
            gstore_B1(rBh, (__half*)(smraw + (cur ^ 1) * BUF1 + ABYTES));
        }
    }
    #pragma unroll
    for (int nt = 0; nt < 4; nt++) {
        int r0 = m0 + wm * 16 + gid;
        int cb = n0 + wn * 32 + nt * 8 + tig * 2;
        g_xr[(size_t)r0 * CC + cb]       = acc[nt][0] + srb[cb];
        g_xr[(size_t)r0 * CC + cb + 1]   = acc[nt][1] + srb[cb + 1];
        g_xr[(size_t)(r0+8) * CC + cb]   = acc[nt][2] + srb[cb];
        g_xr[(size_t)(r0+8) * CC + cb+1] = acc[nt][3] + srb[cb + 1];
    }
}

// ---------------- LayerNorm ----------------
__global__ void __launch_bounds__(256) k_layernorm(const float* __restrict__ gamma,
                                                   const float* __restrict__ beta) {
    int row  = blockIdx.x * 8 + (threadIdx.x >> 5);
    int lane = threadIdx.x & 31;
    float* xr = g_xr + (size_t)row * CC;
    float v[8], s = 0.f;
    #pragma unroll
    for (int i = 0; i < 8; i++) { v[i] = xr[lane + i * 32]; s += v[i]; }
    #pragma unroll
    for (int o = 16; o; o >>= 1) s += __shfl_xor_sync(0xffffffffu, s, o);
    float mu = s * (1.f / 256.f), s2 = 0.f;
    #pragma unroll
    for (int i = 0; i < 8; i++) { float d = v[i] - mu; s2 += d * d; }
    #pragma unroll
    for (int o = 16; o; o >>= 1) s2 += __shfl_xor_sync(0xffffffffu, s2, o);
    float rstd = rsqrtf(s2 * (1.f / 256.f) + 1e-5f);
    #pragma unroll
    for (int i = 0; i < 8; i++) {
        int c = lane + i * 32;
        xr[c] = (v[i] - mu) * rstd * gamma[c] + beta[c];
    }
}

// ---------------- KV projection: M=4096, K=256, N=512 (single-B) ----------------
__global__ void __launch_bounds__(256) k_kv_mma() {
    GEMM_PROLOG
    int n0 = blockIdx.x * 64, m0 = blockIdx.y * 64;
    float2 rA[4]; __half rBh[8];
    gload_A(g_xr, CC, m0, 0, rA);
    gload_B1(g_wkvh, 2 * CC, 0, n0, rBh);
    gstore_A(rA, (__half*)smraw);
    gstore_B1(rBh, (__half*)(smraw + ABYTES));
    for (int k0 = 0; k0 < CC; k0 += 32) {
        int cur = (k0 >> 5) & 1;
        __syncthreads();
        bool more = (k0 + 32 < CC);
        if (more) {
            gload_A(g_xr, CC, m0, k0 + 32, rA);
            gload_B1(g_wkvh, 2 * CC, k0 + 32, n0, rBh);
        }
        uint32_t bu = smemU + cur * BUF1;
        mma_step1(bu, bu + ABYTES, acc, wm, wn, aOff, bOff);
        if (more) {
            gstore_A(rA, (__half*)(smraw + (cur ^ 1) * BUF1));
            gstore_B1(rBh, (__half*)(smraw + (cur ^ 1) * BUF1 + ABYTES));
        }
    }
    #pragma unroll
    for (int nt = 0; nt < 4; nt++)
        #pragma unroll
        for (int e = 0; e < 4; e++) {
            int r = m0 + wm * 16 + gid + (e >= 2 ? 8 : 0);
            int n = n0 + wn * 32 + nt * 8 + tig * 2 + (e & 1);
            int b = r >> 10, pos = r & 1023;
            int half = n >> 8, hh = (n >> 5) & 7, d = n & 31;
            size_t dst = ((size_t)((b * NHH + hh) * NKV + pos)) * HDD + d;
            __half v = __float2half_rn(acc[nt][e]);
            if (half == 0) g_kh[dst] = v; else g_vh[dst] = v;
        }
}

// ---------------- Q projection: M=16384, K=256, N=256 (single-B) ----------------
__global__ void __launch_bounds__(256) k_qproj_mma(const float* __restrict__ q) {
    GEMM_PROLOG
    int n0 = blockIdx.x * 64, m0 = blockIdx.y * 64;
    float2 rA[4]; __half rBh[8];
    gload_A(q, CC, m0, 0, rA);
    gload_B1(g_wqh, CC, 0, n0, rBh);
    gstore_A(rA, (__half*)smraw);
    gstore_B1(rBh, (__half*)(smraw + ABYTES));
    for (int k0 = 0; k0 < CC; k0 += 32) {
        int cur = (k0 >> 5) & 1;
        __syncthreads();
        bool more = (k0 + 32 < CC);
        if (more) {
            gload_A(q, CC, m0, k0 + 32, rA);
            gload_B1(g_wqh, CC, k0 + 32, n0, rBh);
        }
        uint32_t bu = smemU + cur * BUF1;
        mma_step1(bu, bu + ABYTES, acc, wm, wn, aOff, bOff);
        if (more) {
            gstore_A(rA, (__half*)(smraw + (cur ^ 1) * BUF1));
            gstore_B1(rBh, (__half*)(smraw + (cur ^ 1) * BUF1 + ABYTES));
        }
    }
    #pragma unroll
    for (int nt = 0; nt < 4; nt++)
        #pragma unroll
        for (int e = 0; e < 4; e++) {
            int r = m0 + wm * 16 + gid + (e >= 2 ? 8 : 0);
            int n = n0 + wn * 32 + nt * 8 + tig * 2 + (e & 1);
            g_qhh[(size_t)r * CC + n] = __float2half_rn(acc[nt][e]);
        }
}

// ---------------- Output projection: M=16384, K=256, N=256 (split-B) ----------------
__global__ void __launch_bounds__(256) k_proj_mma(const float* __restrict__ bp,
                                                  float* __restrict__ out) {
    GEMM_PROLOG
    int n0 = blockIdx.x * 64, m0 = blockIdx.y * 64;
    float2 rA[4]; __half rBh[8], rBl[8];
    gload_A(g_o, CC, m0, 0, rA);
    gload_B2(g_pwh, g_pwl, CC, 0, n0, rBh, rBl);
    gstore_A(rA, (__half*)smraw);
    gstore_B2(rBh, rBl, (__half*)(smraw + ABYTES), (__half*)(smraw + ABYTES + BBYTES));
    for (int k0 = 0; k0 < CC; k0 += 32) {
        int cur = (k0 >> 5) & 1;
        __syncthreads();
        bool more = (k0 + 32 < CC);
        if (more) {
            gload_A(g_o, CC, m0, k0 + 32, rA);
            gload_B2(g_pwh, g_pwl, CC, k0 + 32, n0, rBh, rBl);
        }
        uint32_t bu = smemU + cur * BUF2;
        mma_step2(bu, bu + ABYTES, bu + ABYTES + BBYTES, acc, wm, wn, aOff, bOff);
        if (more) {
            gstore_A(rA, (__half*)(smraw + (cur ^ 1) * BUF2));
            gstore_B2(rBh, rBl, (__half*)(smraw + (cur ^ 1) * BUF2 + ABYTES),
                      (__half*)(smraw + (cur ^ 1) * BUF2 + ABYTES + BBYTES));
        }
    }
    #pragma unroll
    for (int nt = 0; nt < 4; nt++)
        #pragma unroll
        for (int e = 0; e < 4; e++) {
            int r = m0 + wm * 16 + gid + (e >= 2 ? 8 : 0);
            int n = n0 + wn * 32 + nt * 8 + tig * 2 + (e & 1);
            out[(size_t)r * CC + n] = acc[nt][e] + bp[n];
        }
}

// ---------------- Flash attention (unchanged, proven) ----------------
#define VT_S 130

__global__ void __launch_bounds__(256) k_attn_flash(const int* __restrict__ qlen) {
    __shared__ __half Ks[128 * 40];
    __shared__ __half Vt[32 * VT_S];

    int tid = threadIdx.x;
    int w = tid >> 5, lane = tid & 31;
    int gid = lane >> 2, tig = lane & 3;
    int h = blockIdx.y;
    int q0 = blockIdx.x * 128;

    int l0 = qlen[0], l1 = qlen[1], l2 = qlen[2];
    int b = 0;
    if (q0 >= l0) b = 1;
    if (q0 >= l0 + l1) b = 2;
    if (q0 >= l0 + l1 + l2) b = 3;

    const __half* Kb = g_kh + ((size_t)(b * NHH + h) * NKV) * HDD;
    const __half* Vb = g_vh + ((size_t)(b * NHH + h) * NKV) * HDD;

    uint32_t aQ[2][4];
    {
        const __half* Qp = g_qhh + (size_t)(q0 + w * 16) * CC + h * HDD;
        #pragma unroll
        for (int kc = 0; kc < 2; kc++) {
            int c = kc * 16 + tig * 2;
            aQ[kc][0] = *(const uint32_t*)(Qp + (size_t)gid * CC + c);
            aQ[kc][1] = *(const uint32_t*)(Qp + (size_t)(gid + 8) * CC + c);
            aQ[kc][2] = *(const uint32_t*)(Qp + (size_t)gid * CC + c + 8);
            aQ[kc][3] = *(const uint32_t*)(Qp + (size_t)(gid + 8) * CC + c + 8);
        }
    }

    float o[4][4];
    #pragma unroll
    for (int i = 0; i < 4; i++)
        #pragma unroll
        for (int j = 0; j < 4; j++) o[i][j] = 0.f;
    float mrow[2] = {-1e30f, -1e30f};
    float lsum[2] = {0.f, 0.f};

    for (int kt = 0; kt < 8; kt++) {
        #pragma unroll
        for (int i = 0; i < 8; i++) {
            int idx = tid + i * 256;
            int key = idx >> 4, dp = idx & 15;
            ((uint32_t*)Ks)[key * 20 + dp] =
                *(const uint32_t*)(Kb + (size_t)(kt * 128 + key) * HDD + dp * 2);
        }
        #pragma unroll
        for (int i = 0; i < 8; i++) {
            int idx = tid + i * 256;
            int key = idx >> 4, dp = idx & 15;
            uint32_t u = *(const uint32_t*)(Vb + (size_t)(kt * 128 + key) * HDD + dp * 2);
            __half2 h2 = *(__half2*)&u;
            Vt[(dp * 2) * VT_S + key]     = __low2half(h2);
            Vt[(dp * 2 + 1) * VT_S + key] = __high2half(h2);
        }
        __syncthreads();

        float c[16][4];
        #pragma unroll
        for (int t = 0; t < 16; t++) {
            c[t][0] = c[t][1] = c[t][2] = c[t][3] = 0.f;
            #pragma unroll
            for (int kc = 0; kc < 2; kc++) {
                int cc = kc * 16 + tig * 2;
                uint32_t b0 = *(const uint32_t*)(Ks + (t * 8 + gid) * 40 + cc);
                uint32_t b1 = *(const uint32_t*)(Ks + (t * 8 + gid) * 40 + cc + 8);
                mma16816(c[t], aQ[kc][0], aQ[kc][1], aQ[kc][2], aQ[kc][3], b0, b1);
            }
        }

        float tm0 = -1e30f, tm1 = -1e30f;
        #pragma unroll
        for (int t = 0; t < 16; t++) {
            tm0 = fmaxf(tm0, fmaxf(c[t][0], c[t][1]));
            tm1 = fmaxf(tm1, fmaxf(c[t][2], c[t][3]));
        }
        tm0 = fmaxf(tm0, __shfl_xor_sync(0xffffffffu, tm0, 1));
        tm0 = fmaxf(tm0, __shfl_xor_sync(0xffffffffu, tm0, 2));
        tm1 = fmaxf(tm1, __shfl_xor_sync(0xffffffffu, tm1, 1));
        tm1 = fmaxf(tm1, __shfl_xor_sync(0xffffffffu, tm1, 2));
        float mn0 = fmaxf(mrow[0], tm0);
        float mn1 = fmaxf(mrow[1], tm1);
        float f0 = exp2f((mrow[0] - mn0) * C2E);
        float f1 = exp2f((mrow[1] - mn1) * C2E);
        mrow[0] = mn0; mrow[1] = mn1;
        lsum[0] *= f0; lsum[1] *= f1;
        #pragma unroll
        for (int nt = 0; nt < 4; nt++) {
            o[nt][0] *= f0; o[nt][1] *= f0;
            o[nt][2] *= f1; o[nt][3] *= f1;
        }
        float ps0 = 0.f, ps1 = 0.f;
        uint32_t pf[16][2];
        #pragma unroll
        for (int t = 0; t < 16; t++) {
            float p0 = exp2f((c[t][0] - mn0) * C2E);
            float p1 = exp2f((c[t][1] - mn0) * C2E);
            float p2 = exp2f((c[t][2] - mn1) * C2E);
            float p3 = exp2f((c[t][3] - mn1) * C2E);
            ps0 += p0 + p1;
            ps1 += p2 + p3;
            pf[t][0] = pack2(__float2half_rn(p0), __float2half_rn(p1));
            pf[t][1] = pack2(__float2half_rn(p2), __float2half_rn(p3));
        }
        lsum[0] += ps0;
        lsum[1] += ps1;

        #pragma unroll
        for (int j = 0; j < 8; j++) {
            uint32_t a0 = pf[2 * j][0];
            uint32_t a1 = pf[2 * j][1];
            uint32_t a2 = pf[2 * j + 1][0];
            uint32_t a3 = pf[2 * j + 1][1];
            #pragma unroll
            for (int nt = 0; nt < 4; nt++) {
                int d = nt * 8 + gid;
                uint32_t b0 = *(const uint32_t*)(Vt + d * VT_S + 16 * j + tig * 2);
                uint32_t b1 = *(const uint32_t*)(Vt + d * VT_S + 16 * j + tig * 2 + 8);
                mma16816(o[nt], a0, a1, a2, a3, b0, b1);
            }
        }
        __syncthreads();
    }

    lsum[0] += __shfl_xor_sync(0xffffffffu, lsum[0], 1);
    lsum[0] += __shfl_xor_sync(0xffffffffu, lsum[0], 2);
    lsum[1] += __shfl_xor_sync(0xffffffffu, lsum[1], 1);
    lsum[1] += __shfl_xor_sync(0xffffffffu, lsum[1], 2);

    float i0 = 1.f / lsum[0], i1 = 1.f / lsum[1];
    float* Op = g_o + (size_t)(q0 + w * 16) * CC + h * HDD;
    #pragma unroll
    for (int nt = 0; nt < 4; nt++) {
        int col = nt * 8 + tig * 2;
        float2 v0 = make_float2(o[nt][0] * i0, o[nt][1] * i0);
        float2 v1 = make_float2(o[nt][2] * i1, o[nt][3] * i1);
        *(float2*)(Op + (size_t)gid * CC + col)       = v0;
        *(float2*)(Op + (size_t)(gid + 8) * CC + col) = v1;
    }
}

// ---------------- launch ----------------
extern "C" void kernel_launch(void* const* d_in, const int* in_sizes, int n_in,
                              void* d_out, int out_size) {
    const float* x      = (const float*)d_in[0];
    const float* q      = (const float*)d_in[1];
    const int*   qlen   = (const int*)  d_in[4];
    const float* w_q    = (const float*)d_in[5];
    const float* w_kv   = (const float*)d_in[6];
    const float* sr_w   = (const float*)d_in[7];
    const float* sr_b   = (const float*)d_in[8];
    const float* ln_g   = (const float*)d_in[9];
    const float* ln_b   = (const float*)d_in[10];
    const float* proj_w = (const float*)d_in[11];
    const float* proj_b = (const float*)d_in[12];
    float* out = (float*)d_out;

    cudaFuncSetAttribute(k_conv_mma,  cudaFuncAttributeMaxDynamicSharedMemorySize, SMEM1);
    cudaFuncSetAttribute(k_kv_mma,    cudaFuncAttributeMaxDynamicSharedMemorySize, SMEM1);
    cudaFuncSetAttribute(k_qproj_mma, cudaFuncAttributeMaxDynamicSharedMemorySize, SMEM1);
    cudaFuncSetAttribute(k_proj_mma,  cudaFuncAttributeMaxDynamicSharedMemorySize, SMEM2);

    __half *wqh, *wkvh, *pwh, *pwl;
    cudaGetSymbolAddress((void**)&wqh,  g_wqh);
    cudaGetSymbolAddress((void**)&wkvh, g_wkvh);
    cudaGetSymbolAddress((void**)&pwh,  g_pwh);
    cudaGetSymbolAddress((void**)&pwl,  g_pwl);

    k_cvt<<<(CC*CC + 255)/256, 256>>>(w_q, wqh, CC*CC);
    k_cvt<<<(CC*2*CC + 255)/256, 256>>>(w_kv, wkvh, CC*2*CC);
    k_split<<<(CC*CC + 255)/256, 256>>>(proj_w, pwh, pwl, CC*CC);
    k_cvt_srw<<<(KCONV*CC + 255)/256, 256>>>(sr_w);

    k_conv_mma<<<dim3(CC/64, (BB*NKV)/64), 256, SMEM1>>>(x, sr_b);
    k_layernorm<<<(BB*NKV)/8, 256>>>(ln_g, ln_b);
    k_kv_mma<<<dim3((2*CC)/64, (BB*NKV)/64), 256, SMEM1>>>();
    k_qproj_mma<<<dim3(CC/64, TQ/64), 256, SMEM1>>>(q);
    k_attn_flash<<<dim3(TQ/128, NHH), 256>>>(qlen);
    k_proj_mma<<<dim3(CC/64, TQ/64), 256, SMEM2>>>(proj_b, out);
}